// round 10
// baseline (speedup 1.0000x reference)
#include <cuda_runtime.h>
#include <math.h>

#define BB 8
#define NN 4096
#define KK 20
#define BN (BB*NN)

// ---------------- scratch (static device globals; no runtime alloc) ----------------
__device__ float g_x0[BN*6];
__device__ float g_xcat[(size_t)BN*512];
__device__ float g_A[(size_t)BN*256];
__device__ float g_C[(size_t)BN*256];
__device__ float g_sq[BN];
__device__ int   g_knn[BN*KK];
__device__ int   g_pool_enc[BB*1024];
__device__ float g_h1[BB*512];
__device__ float g_h2[BB*256];

__device__ __forceinline__ int   encf(float f){ int i=__float_as_int(f); return i>=0 ? i : i^0x7FFFFFFF; }
__device__ __forceinline__ float decf(int i){ return __int_as_float(i>=0 ? i : i^0x7FFFFFFF); }
#define ENC_NEG_INF (-2139095041)  /* encf(-inf) = 0x807FFFFF */

// ---------------- build x0 = concat(pos, x) ----------------
__global__ void build_x0_kernel(const float* __restrict__ pos, const float* __restrict__ x) {
    int g = blockIdx.x * 256 + threadIdx.x;
    if (g >= BN*6) return;
    int n = g / 6, c = g - n*6;
    g_x0[g] = (c < 3) ? pos[n*3 + c] : x[n*3 + c - 3];
}

__global__ void init_pool_kernel() {
    int g = blockIdx.x * 256 + threadIdx.x;
    if (g < BB*1024) g_pool_enc[g] = ENC_NEG_INF;
}

// ---------------- squared norms ----------------
template<int CIN, int SIN, bool USE_X0, int INOFF>
__global__ void sq_kernel() {
    int g = blockIdx.x * 256 + threadIdx.x;
    if (g >= BN) return;
    const float* base = USE_X0 ? g_x0 : (g_xcat + INOFF);
    const float* xr = base + (size_t)g * SIN;
    float s = 0.f;
    #pragma unroll 8
    for (int c = 0; c < CIN; c++) { float v = xr[c]; s += v*v; }
    g_sq[g] = s;
}

// ---------------- kNN: 4-way j-split, register top-20 per split, shared merge ----------
// 64 nodes/block x 4 splits = 256 threads. Thread (nl,sp) scans j in
// [sp*1024, (sp+1)*1024) keeping a register-resident sorted top-20 (static-index
// rolling insert). Splits 1..3 dump sorted lists to shared; split 0 merge-inserts
// (early exit on sorted candidates) and writes the final 20 indices.
template<int CIN> __host__ __device__ constexpr int knn_xis_stride() { return CIN + 4; }
template<int CIN> __host__ __device__ constexpr int knn_xj_stride()  { return 16*CIN + 8; }
template<int CIN> __host__ __device__ constexpr int knn_xj_region()  {
    return (4*knn_xj_stride<CIN>() > 2*192*KK) ? 4*knn_xj_stride<CIN>() : 2*192*KK;
}
template<int CIN> __host__ __device__ constexpr int knn_smem_bytes() {
    return (64*knn_xis_stride<CIN>() + knn_xj_region<CIN>()) * 4;
}

template<int CIN, int SIN, bool USE_X0, int INOFF>
__global__ void __launch_bounds__(256, 2) knn_kernel() {
    constexpr int TI = 64, SPLIT = 4, TJ = 16;
    constexpr int JSEG = NN / SPLIT;                 // 1024
    constexpr int XIS_STRIDE = knn_xis_stride<CIN>();
    constexpr int XJ_STRIDE  = knn_xj_stride<CIN>();
    constexpr int MERGE_FLOATS = 192*KK;             // 3 splits * 64 nodes * 20

    extern __shared__ float smem[];
    float* Xis = smem;                               // TI * XIS_STRIDE
    float* Xjs = smem + TI*XIS_STRIDE;               // XJ region (reused for merge)
    __shared__ float sqj_s[SPLIT*TJ];

    const int b   = blockIdx.y;
    const int tid = threadIdx.x;
    const int nl  = tid >> 2;        // node-local 0..63
    const int sp  = tid & 3;         // split 0..3
    const int i   = blockIdx.x*TI + nl;
    const float* base = USE_X0 ? g_x0 : (g_xcat + INOFF);
    const float* Xb = base + (size_t)b * NN * SIN;

    // stage this block's 64 xi rows (coalesced; synced by first loop barrier)
    for (int e = tid; e < TI*CIN; e += 256) {
        int r = e / CIN, c = e - r*CIN;
        Xis[r*XIS_STRIDE + c] = Xb[(size_t)(blockIdx.x*TI + r)*SIN + c];
    }

    float kd[KK]; int ki[KK];
    #pragma unroll
    for (int k = 0; k < KK; k++) { kd[k] = 3.4e38f; ki[k] = 0; }

    const float sqi = g_sq[b*NN + i];
    float thr = 3.3e38f;             // = worst - sqi (clamped huge initially)

    const int jbase = sp * JSEG;
    const float* xi = Xis + nl*XIS_STRIDE;
    const float* xj = Xjs + sp*XJ_STRIDE;

    for (int jo = 0; jo < JSEG; jo += TJ) {
        __syncthreads();
        // stage all 4 splits' j-tiles (4*TJ*CIN floats, coalesced)
        for (int e = tid; e < SPLIT*TJ*CIN; e += 256) {
            int s = e / (TJ*CIN);
            int rem = e - s*(TJ*CIN);
            int r = rem / CIN, c = rem - r*CIN;
            Xjs[s*XJ_STRIDE + r*CIN + c] = Xb[(size_t)(s*JSEG + jo + r)*SIN + c];
        }
        if (tid < SPLIT*TJ)
            sqj_s[tid] = g_sq[b*NN + (tid>>4)*JSEG + jo + (tid&15)];
        __syncthreads();

        float acc[TJ];
        #pragma unroll
        for (int j = 0; j < TJ; j++) acc[j] = 0.f;

        if (CIN % 4 == 0) {
            #pragma unroll 4
            for (int c4 = 0; c4 < CIN/4; c4++) {
                const float a0 = xi[c4*4+0];
                const float a1 = xi[c4*4+1];
                const float a2 = xi[c4*4+2];
                const float a3 = xi[c4*4+3];
                #pragma unroll
                for (int j = 0; j < TJ; j++) {
                    const float4 b4 = *reinterpret_cast<const float4*>(&xj[j*CIN + c4*4]);
                    acc[j] = fmaf(a0, b4.x, acc[j]);
                    acc[j] = fmaf(a1, b4.y, acc[j]);
                    acc[j] = fmaf(a2, b4.z, acc[j]);
                    acc[j] = fmaf(a3, b4.w, acc[j]);
                }
            }
        } else {
            #pragma unroll
            for (int c = 0; c < CIN; c++) {
                const float xv = xi[c];
                #pragma unroll
                for (int j = 0; j < TJ; j++) acc[j] = fmaf(xv, xj[j*CIN + c], acc[j]);
            }
        }

        #pragma unroll
        for (int j = 0; j < TJ; j++) {
            float r2 = sqj_s[sp*TJ + j] - 2.f*acc[j];   // d - sqi
            if (r2 < thr) {
                float cd = r2 + sqi; int ci = jbase + jo + j;
                #pragma unroll
                for (int k = 0; k < KK; k++) {
                    const bool sw = cd < kd[k];
                    const float nd = sw ? kd[k] : cd;
                    const int   ni = sw ? ki[k] : ci;
                    kd[k] = sw ? cd : kd[k];
                    ki[k] = sw ? ci : ki[k];
                    cd = nd; ci = ni;
                }
                thr = kd[KK-1] - sqi;
            }
        }
    }

    // ---- merge: splits 1..3 publish sorted lists; split 0 folds them in ----
    __syncthreads();                         // main-loop reads of Xjs done
    float* md = Xjs;
    int*   mi = (int*)(Xjs + MERGE_FLOATS);
    if (sp != 0) {
        const int o = (nl*3 + (sp-1))*KK;
        #pragma unroll
        for (int k = 0; k < KK; k++) { md[o+k] = kd[k]; mi[o+k] = ki[k]; }
    }
    __syncthreads();
    if (sp == 0) {
        float worst = kd[KK-1];
        #pragma unroll
        for (int s = 0; s < 3; s++) {
            const int o = (nl*3 + s)*KK;
            for (int k = 0; k < KK; k++) {
                float cd = md[o+k];
                if (cd >= worst) break;      // source list sorted ascending
                int ci = mi[o+k];
                #pragma unroll
                for (int kk = 0; kk < KK; kk++) {
                    const bool sw = cd < kd[kk];
                    const float nd = sw ? kd[kk] : cd;
                    const int   ni = sw ? ki[kk] : ci;
                    kd[kk] = sw ? cd : kd[kk];
                    ki[kk] = sw ? ci : ki[kk];
                    cd = nd; ci = ni;
                }
                worst = kd[KK-1];
            }
        }
        int* dst = g_knn + (size_t)(b*NN + i)*KK;
        #pragma unroll
        for (int k = 0; k < KK; k++) dst[k] = ki[k];
    }
}

// ---------------- per-node projections: A = X(Wt-Wb)+b, C = X Wb ----------------
template<int CIN, int SIN, bool USE_X0, int INOFF, int COUT>
__global__ void __launch_bounds__(256) proj_kernel(const float* __restrict__ W,
                                                   const float* __restrict__ bias) {
    constexpr int TM = 16;
    constexpr int STRIP = COUT / 16;        // 4, 8, or 16 (all %4==0)
    __shared__ float xs[TM][CIN];

    const int nodeBase = blockIdx.x * TM;
    const int tid = threadIdx.x;
    const float* base = USE_X0 ? g_x0 : (g_xcat + INOFF);

    for (int e = tid; e < TM*CIN; e += 256) {
        int r = e / CIN, c = e - r*CIN;
        xs[r][c] = base[(size_t)(nodeBase + r)*SIN + c];
    }
    __syncthreads();

    const int node = tid >> 4;
    const int cg   = tid & 15;
    const int co   = cg * STRIP;

    float accA[STRIP], accC[STRIP];
    #pragma unroll
    for (int s = 0; s < STRIP; s++) { accA[s] = 0.f; accC[s] = 0.f; }

    #pragma unroll 4
    for (int c = 0; c < CIN; c++) {
        float xv = xs[node][c];
        const float4* wt = reinterpret_cast<const float4*>(W + (size_t)c*COUT + co);
        const float4* wb = reinterpret_cast<const float4*>(W + (size_t)(CIN + c)*COUT + co);
        #pragma unroll
        for (int u = 0; u < STRIP/4; u++) {
            float4 t4 = __ldg(wt + u);
            float4 b4 = __ldg(wb + u);
            accA[4*u+0] = fmaf(xv, t4.x - b4.x, accA[4*u+0]);
            accA[4*u+1] = fmaf(xv, t4.y - b4.y, accA[4*u+1]);
            accA[4*u+2] = fmaf(xv, t4.z - b4.z, accA[4*u+2]);
            accA[4*u+3] = fmaf(xv, t4.w - b4.w, accA[4*u+3]);
            accC[4*u+0] = fmaf(xv, b4.x, accC[4*u+0]);
            accC[4*u+1] = fmaf(xv, b4.y, accC[4*u+1]);
            accC[4*u+2] = fmaf(xv, b4.z, accC[4*u+2]);
            accC[4*u+3] = fmaf(xv, b4.w, accC[4*u+3]);
        }
    }
    size_t rowo = (size_t)(nodeBase + node)*COUT + co;
    #pragma unroll
    for (int s = 0; s < STRIP; s++) {
        g_A[rowo + s] = accA[s] + bias[co + s];
        g_C[rowo + s] = accC[s];
    }
}

// ---------------- gather-max aggregate: out = A[i] + max_k C[knn(i,k)] ----------------
template<int COUT, int CATOFF>
__global__ void agg_kernel() {
    const int node = blockIdx.x;
    const int c = threadIdx.x;
    __shared__ int sidx[KK];
    if (c < KK) sidx[c] = g_knn[(size_t)node*KK + c];
    __syncthreads();
    const int jb = (node >> 12) << 12;   // batch base (NN = 4096)
    float m = -3.4e38f;
    #pragma unroll
    for (int k = 0; k < KK; k++)
        m = fmaxf(m, g_C[(size_t)(jb + sidx[k])*COUT + c]);
    g_xcat[(size_t)node*512 + CATOFF + c] = g_A[(size_t)node*COUT + c] + m;
}

// ---------------- final GEMM [BN,512]x[512,1024] fused with max over N ----------------
__global__ void __launch_bounds__(256) final_kernel(const float* __restrict__ Wf1,
                                                    const float* __restrict__ bf1) {
    __shared__ float As[16][132];   // [k][node]
    __shared__ float Bs[16][132];   // [k][out]
    __shared__ int cmax[128];

    const int tid = threadIdx.x;
    const int nodeBase = blockIdx.x * 128;
    const int outBase  = blockIdx.y * 128;
    const int rb = (tid >> 4) * 8;
    const int cb = (tid & 15) * 8;

    float acc[8][8];
    #pragma unroll
    for (int u = 0; u < 8; u++)
        #pragma unroll
        for (int v = 0; v < 8; v++) acc[u][v] = 0.f;

    for (int kc = 0; kc < 512; kc += 16) {
        __syncthreads();
        for (int e = tid; e < 128*16; e += 256) {
            int node = e >> 4, k = e & 15;
            As[k][node] = g_xcat[(size_t)(nodeBase + node)*512 + kc + k];
        }
        for (int e = tid; e < 16*128; e += 256) {
            int k = e >> 7, o = e & 127;
            Bs[k][o] = Wf1[(size_t)(kc + k)*1024 + outBase + o];
        }
        __syncthreads();
        #pragma unroll
        for (int k = 0; k < 16; k++) {
            float4 a0 = *reinterpret_cast<const float4*>(&As[k][rb]);
            float4 a1 = *reinterpret_cast<const float4*>(&As[k][rb+4]);
            float4 b0 = *reinterpret_cast<const float4*>(&Bs[k][cb]);
            float4 b1 = *reinterpret_cast<const float4*>(&Bs[k][cb+4]);
            float av[8] = {a0.x,a0.y,a0.z,a0.w,a1.x,a1.y,a1.z,a1.w};
            float bv[8] = {b0.x,b0.y,b0.z,b0.w,b1.x,b1.y,b1.z,b1.w};
            #pragma unroll
            for (int u = 0; u < 8; u++)
                #pragma unroll
                for (int v = 0; v < 8; v++) acc[u][v] = fmaf(av[u], bv[v], acc[u][v]);
        }
    }

    if (tid < 128) cmax[tid] = ENC_NEG_INF;
    __syncthreads();

    const int b = nodeBase >> 12;
    #pragma unroll
    for (int v = 0; v < 8; v++) {
        float colm = -3.4e38f;
        #pragma unroll
        for (int u = 0; u < 8; u++) colm = fmaxf(colm, acc[u][v]);
        colm += bf1[outBase + cb + v];
        atomicMax(&cmax[cb + v], encf(colm));
    }
    __syncthreads();
    if (tid < 128) atomicMax(&g_pool_enc[b*1024 + outBase + tid], cmax[tid]);
}

// ---------------- head ----------------
__global__ void head1_kernel(const float* __restrict__ Wa, const float* __restrict__ ba) {
    const int b = blockIdx.x, o = threadIdx.x;   // 512 threads
    __shared__ float p[1024];
    for (int e = o; e < 1024; e += 512) p[e] = decf(g_pool_enc[b*1024 + e]);
    __syncthreads();
    float acc = ba[o];
    #pragma unroll 8
    for (int in = 0; in < 1024; in++) acc = fmaf(p[in], Wa[(size_t)in*512 + o], acc);
    g_h1[b*512 + o] = fmaxf(acc, 0.f);
}

__global__ void head2_kernel(const float* __restrict__ Wb, const float* __restrict__ bb) {
    const int b = blockIdx.x, o = threadIdx.x;   // 256 threads
    __shared__ float p[512];
    for (int e = o; e < 512; e += 256) p[e] = g_h1[b*512 + e];
    __syncthreads();
    float acc = bb[o];
    #pragma unroll 8
    for (int in = 0; in < 512; in++) acc = fmaf(p[in], Wb[(size_t)in*256 + o], acc);
    g_h2[b*256 + o] = fmaxf(acc, 0.f);
}

__global__ void head3_kernel(const float* __restrict__ Wc, const float* __restrict__ bc,
                             float* __restrict__ out) {
    const int b = blockIdx.x, t = threadIdx.x;   // 32 threads
    __shared__ float h[256];
    for (int e = t; e < 256; e += 32) h[e] = g_h2[b*256 + e];
    __syncthreads();
    float logit = -3.4e38f;
    if (t < 23) {
        logit = bc[t];
        #pragma unroll 8
        for (int in = 0; in < 256; in++) logit = fmaf(h[in], Wc[in*23 + t], logit);
    }
    float mx = logit;
    #pragma unroll
    for (int off = 16; off > 0; off >>= 1) mx = fmaxf(mx, __shfl_xor_sync(0xffffffffu, mx, off));
    float ex = (t < 23) ? expf(logit - mx) : 0.f;
    float s = ex;
    #pragma unroll
    for (int off = 16; off > 0; off >>= 1) s += __shfl_xor_sync(0xffffffffu, s, off);
    if (t < 23) out[b*23 + t] = logit - mx - logf(s);
}

// ---------------- launch ----------------
extern "C" void kernel_launch(void* const* d_in, const int* in_sizes, int n_in,
                              void* d_out, int out_size) {
    const float* pos = (const float*)d_in[0];
    const float* x   = (const float*)d_in[1];
    const float* W1  = (const float*)d_in[2];  const float* b1 = (const float*)d_in[3];
    const float* W2  = (const float*)d_in[4];  const float* b2 = (const float*)d_in[5];
    const float* W3  = (const float*)d_in[6];  const float* b3 = (const float*)d_in[7];
    const float* W4  = (const float*)d_in[8];  const float* b4 = (const float*)d_in[9];
    const float* Wf1 = (const float*)d_in[10]; const float* bf1 = (const float*)d_in[11];
    const float* Wa  = (const float*)d_in[12]; const float* ba = (const float*)d_in[13];
    const float* Wb  = (const float*)d_in[14]; const float* bb = (const float*)d_in[15];
    const float* Wc  = (const float*)d_in[16]; const float* bc = (const float*)d_in[17];
    float* out = (float*)d_out;

    // allow >48KB dynamic smem where needed (host-side config, not a stream op;
    // legal during graph capture and idempotent across calls)
    cudaFuncSetAttribute(knn_kernel<6,   6,   true,  0>,   cudaFuncAttributeMaxDynamicSharedMemorySize, knn_smem_bytes<6>());
    cudaFuncSetAttribute(knn_kernel<64,  512, false, 0>,   cudaFuncAttributeMaxDynamicSharedMemorySize, knn_smem_bytes<64>());
    cudaFuncSetAttribute(knn_kernel<64,  512, false, 64>,  cudaFuncAttributeMaxDynamicSharedMemorySize, knn_smem_bytes<64>());
    cudaFuncSetAttribute(knn_kernel<128, 512, false, 128>, cudaFuncAttributeMaxDynamicSharedMemorySize, knn_smem_bytes<128>());

    build_x0_kernel<<<(BN*6 + 255)/256, 256>>>(pos, x);
    init_pool_kernel<<<(BB*1024 + 255)/256, 256>>>();

    // layer 1: x0 (CIN=6, stride 6) -> x1 (64) @ cat offset 0
    sq_kernel<6, 6, true, 0><<<BN/256, 256>>>();
    knn_kernel<6, 6, true, 0><<<dim3(NN/64, BB), 256, knn_smem_bytes<6>()>>>();
    proj_kernel<6, 6, true, 0, 64><<<BN/16, 256>>>(W1, b1);
    agg_kernel<64, 0><<<BN, 64>>>();

    // layer 2: x1 (CIN=64, stride 512, off 0) -> x2 (64) @ cat offset 64
    sq_kernel<64, 512, false, 0><<<BN/256, 256>>>();
    knn_kernel<64, 512, false, 0><<<dim3(NN/64, BB), 256, knn_smem_bytes<64>()>>>();
    proj_kernel<64, 512, false, 0, 64><<<BN/16, 256>>>(W2, b2);
    agg_kernel<64, 64><<<BN, 64>>>();

    // layer 3: x2 (CIN=64, off 64) -> x3 (128) @ cat offset 128
    sq_kernel<64, 512, false, 64><<<BN/256, 256>>>();
    knn_kernel<64, 512, false, 64><<<dim3(NN/64, BB), 256, knn_smem_bytes<64>()>>>();
    proj_kernel<64, 512, false, 64, 128><<<BN/16, 256>>>(W3, b3);
    agg_kernel<128, 128><<<BN, 128>>>();

    // layer 4: x3 (CIN=128, off 128) -> x4 (256) @ cat offset 256
    sq_kernel<128, 512, false, 128><<<BN/256, 256>>>();
    knn_kernel<128, 512, false, 128><<<dim3(NN/64, BB), 256, knn_smem_bytes<128>()>>>();
    proj_kernel<128, 512, false, 128, 256><<<BN/16, 256>>>(W4, b4);
    agg_kernel<256, 256><<<BN, 256>>>();

    // final feature GEMM + global max-pool
    final_kernel<<<dim3(BN/128, 1024/128), 256>>>(Wf1, bf1);

    // head
    head1_kernel<<<BB, 512>>>(Wa, ba);
    head2_kernel<<<BB, 256>>>(Wb, bb);
    head3_kernel<<<BB, 32>>>(Wc, bc, out);
}

// round 11
// speedup vs baseline: 1.0225x; 1.0225x over previous
#include <cuda_runtime.h>
#include <math.h>

#define BB 8
#define NN 4096
#define KK 20
#define BN (BB*NN)

// ---------------- scratch (static device globals; no runtime alloc) ----------------
__device__ float g_x0[BN*6];
__device__ float g_xcat[(size_t)BN*512];
__device__ float g_A[(size_t)BN*256];
__device__ float g_C[(size_t)BN*256];
__device__ float g_sq[BN];
__device__ int   g_knn[BN*KK];
__device__ int   g_pool_enc[BB*1024];
__device__ float g_h1[BB*512];
__device__ float g_h2[BB*256];

__device__ __forceinline__ int   encf(float f){ int i=__float_as_int(f); return i>=0 ? i : i^0x7FFFFFFF; }
__device__ __forceinline__ float decf(int i){ return __int_as_float(i>=0 ? i : i^0x7FFFFFFF); }
#define ENC_NEG_INF (-2139095041)  /* encf(-inf) = 0x807FFFFF */

// ---------------- build x0 = concat(pos, x) ----------------
__global__ void build_x0_kernel(const float* __restrict__ pos, const float* __restrict__ x) {
    int g = blockIdx.x * 256 + threadIdx.x;
    if (g >= BN*6) return;
    int n = g / 6, c = g - n*6;
    g_x0[g] = (c < 3) ? pos[n*3 + c] : x[n*3 + c - 3];
}

__global__ void init_pool_kernel() {
    int g = blockIdx.x * 256 + threadIdx.x;
    if (g < BB*1024) g_pool_enc[g] = ENC_NEG_INF;
}

// ---------------- squared norms ----------------
template<int CIN, int SIN, bool USE_X0, int INOFF>
__global__ void sq_kernel() {
    int g = blockIdx.x * 256 + threadIdx.x;
    if (g >= BN) return;
    const float* base = USE_X0 ? g_x0 : (g_xcat + INOFF);
    const float* xr = base + (size_t)g * SIN;
    float s = 0.f;
    #pragma unroll 8
    for (int c = 0; c < CIN; c++) { float v = xr[c]; s += v*v; }
    g_sq[g] = s;
}

// ---------------- kNN: 4-way j-split with WARP-SHARED pruning threshold ----------
// 64 nodes/block x 4 splits = 256 threads; the 4 splits of a node are adjacent
// lanes of one warp. Each split keeps a register-resident sorted top-20 of
// r2 = sqj - 2*dot (ranking invariant: true dist = r2 + sqi, sqi const per node).
// After every 16-j tile the splits exchange their 20th-best via 2 shfl.xor and
// prune with thr = min over splits — a provable upper bound on the global 20th,
// so pruned candidates can never be in the global top-20. This keeps total
// insert work near the sequential optimum (~106/node) instead of 4x78.
// Merge: splits 1..3 publish sorted lists; split 0 folds them (early exit).
template<int CIN> __host__ __device__ constexpr int knn_xis_stride() { return CIN + 4; }
template<int CIN> __host__ __device__ constexpr int knn_xj_stride()  { return 16*CIN + 8; }
template<int CIN> __host__ __device__ constexpr int knn_xj_region()  {
    return (4*knn_xj_stride<CIN>() > 2*192*KK) ? 4*knn_xj_stride<CIN>() : 2*192*KK;
}
template<int CIN> __host__ __device__ constexpr int knn_smem_bytes() {
    return (64*knn_xis_stride<CIN>() + knn_xj_region<CIN>()) * 4;
}

template<int CIN, int SIN, bool USE_X0, int INOFF>
__global__ void __launch_bounds__(256, 2) knn_kernel() {
    constexpr int TI = 64, SPLIT = 4, TJ = 16;
    constexpr int JSEG = NN / SPLIT;                 // 1024
    constexpr int XIS_STRIDE = knn_xis_stride<CIN>();
    constexpr int XJ_STRIDE  = knn_xj_stride<CIN>();
    constexpr int MERGE_FLOATS = 192*KK;             // 3 splits * 64 nodes * 20

    extern __shared__ float smem[];
    float* Xis = smem;                               // TI * XIS_STRIDE
    float* Xjs = smem + TI*XIS_STRIDE;               // XJ region (reused for merge)
    __shared__ float sqj_s[SPLIT*TJ];

    const int b   = blockIdx.y;
    const int tid = threadIdx.x;
    const int nl  = tid >> 2;        // node-local 0..63
    const int sp  = tid & 3;         // split 0..3
    const int i   = blockIdx.x*TI + nl;
    const float* base = USE_X0 ? g_x0 : (g_xcat + INOFF);
    const float* Xb = base + (size_t)b * NN * SIN;

    // stage this block's 64 xi rows (coalesced; synced by first loop barrier)
    for (int e = tid; e < TI*CIN; e += 256) {
        int r = e / CIN, c = e - r*CIN;
        Xis[r*XIS_STRIDE + c] = Xb[(size_t)(blockIdx.x*TI + r)*SIN + c];
    }

    // top-20 of r2 values (sorted ascending), register resident
    float kd[KK]; int ki[KK];
    #pragma unroll
    for (int k = 0; k < KK; k++) { kd[k] = 3.4e38f; ki[k] = 0; }
    float thr = 3.4e38f;             // shared (min over splits) pruning bound

    const int jbase = sp * JSEG;
    const float* xi = Xis + nl*XIS_STRIDE;
    const float* xj = Xjs + sp*XJ_STRIDE;

    for (int jo = 0; jo < JSEG; jo += TJ) {
        __syncthreads();
        // stage all 4 splits' j-tiles (4*TJ*CIN floats, coalesced)
        for (int e = tid; e < SPLIT*TJ*CIN; e += 256) {
            int s = e / (TJ*CIN);
            int rem = e - s*(TJ*CIN);
            int r = rem / CIN, c = rem - r*CIN;
            Xjs[s*XJ_STRIDE + r*CIN + c] = Xb[(size_t)(s*JSEG + jo + r)*SIN + c];
        }
        if (tid < SPLIT*TJ)
            sqj_s[tid] = g_sq[b*NN + (tid>>4)*JSEG + jo + (tid&15)];
        __syncthreads();

        float acc[TJ];
        #pragma unroll
        for (int j = 0; j < TJ; j++) acc[j] = 0.f;

        if (CIN % 4 == 0) {
            #pragma unroll 4
            for (int c4 = 0; c4 < CIN/4; c4++) {
                const float a0 = xi[c4*4+0];
                const float a1 = xi[c4*4+1];
                const float a2 = xi[c4*4+2];
                const float a3 = xi[c4*4+3];
                #pragma unroll
                for (int j = 0; j < TJ; j++) {
                    const float4 b4 = *reinterpret_cast<const float4*>(&xj[j*CIN + c4*4]);
                    acc[j] = fmaf(a0, b4.x, acc[j]);
                    acc[j] = fmaf(a1, b4.y, acc[j]);
                    acc[j] = fmaf(a2, b4.z, acc[j]);
                    acc[j] = fmaf(a3, b4.w, acc[j]);
                }
            }
        } else {
            #pragma unroll
            for (int c = 0; c < CIN; c++) {
                const float xv = xi[c];
                #pragma unroll
                for (int j = 0; j < TJ; j++) acc[j] = fmaf(xv, xj[j*CIN + c], acc[j]);
            }
        }

        #pragma unroll
        for (int j = 0; j < TJ; j++) {
            float r2 = sqj_s[sp*TJ + j] - 2.f*acc[j];   // dist - sqi (rank-equivalent)
            if (r2 < thr) {
                float cd = r2; int ci = jbase + jo + j;
                #pragma unroll
                for (int k = 0; k < KK; k++) {
                    const bool sw = cd < kd[k];
                    const float nd = sw ? kd[k] : cd;
                    const int   ni = sw ? ki[k] : ci;
                    kd[k] = sw ? cd : kd[k];
                    ki[k] = sw ? ci : ki[k];
                    cd = nd; ci = ni;
                }
            }
        }

        // exchange pruning bound across the node's 4 splits (same warp, adjacent lanes)
        {
            float w = kd[KK-1];
            w = fminf(w, __shfl_xor_sync(0xffffffffu, w, 1));
            w = fminf(w, __shfl_xor_sync(0xffffffffu, w, 2));
            thr = w;
        }
    }

    // ---- merge: splits 1..3 publish sorted lists; split 0 folds them in ----
    __syncthreads();                         // main-loop reads of Xjs done
    float* md = Xjs;
    int*   mi = (int*)(Xjs + MERGE_FLOATS);
    if (sp != 0) {
        const int o = (nl*3 + (sp-1))*KK;
        #pragma unroll
        for (int k = 0; k < KK; k++) { md[o+k] = kd[k]; mi[o+k] = ki[k]; }
    }
    __syncthreads();
    if (sp == 0) {
        float worst = kd[KK-1];
        #pragma unroll
        for (int s = 0; s < 3; s++) {
            const int o = (nl*3 + s)*KK;
            for (int k = 0; k < KK; k++) {
                float cd = md[o+k];
                if (cd >= worst) break;      // source list sorted ascending
                int ci = mi[o+k];
                #pragma unroll
                for (int kk = 0; kk < KK; kk++) {
                    const bool sw = cd < kd[kk];
                    const float nd = sw ? kd[kk] : cd;
                    const int   ni = sw ? ki[kk] : ci;
                    kd[kk] = sw ? cd : kd[kk];
                    ki[kk] = sw ? ci : ki[kk];
                    cd = nd; ci = ni;
                }
                worst = kd[KK-1];
            }
        }
        int* dst = g_knn + (size_t)(b*NN + i)*KK;
        #pragma unroll
        for (int k = 0; k < KK; k++) dst[k] = ki[k];
    }
}

// ---------------- per-node projections: A = X(Wt-Wb)+b, C = X Wb ----------------
template<int CIN, int SIN, bool USE_X0, int INOFF, int COUT>
__global__ void __launch_bounds__(256) proj_kernel(const float* __restrict__ W,
                                                   const float* __restrict__ bias) {
    constexpr int TM = 16;
    constexpr int STRIP = COUT / 16;        // 4, 8, or 16 (all %4==0)
    __shared__ float xs[TM][CIN];

    const int nodeBase = blockIdx.x * TM;
    const int tid = threadIdx.x;
    const float* base = USE_X0 ? g_x0 : (g_xcat + INOFF);

    for (int e = tid; e < TM*CIN; e += 256) {
        int r = e / CIN, c = e - r*CIN;
        xs[r][c] = base[(size_t)(nodeBase + r)*SIN + c];
    }
    __syncthreads();

    const int node = tid >> 4;
    const int cg   = tid & 15;
    const int co   = cg * STRIP;

    float accA[STRIP], accC[STRIP];
    #pragma unroll
    for (int s = 0; s < STRIP; s++) { accA[s] = 0.f; accC[s] = 0.f; }

    #pragma unroll 4
    for (int c = 0; c < CIN; c++) {
        float xv = xs[node][c];
        const float4* wt = reinterpret_cast<const float4*>(W + (size_t)c*COUT + co);
        const float4* wb = reinterpret_cast<const float4*>(W + (size_t)(CIN + c)*COUT + co);
        #pragma unroll
        for (int u = 0; u < STRIP/4; u++) {
            float4 t4 = __ldg(wt + u);
            float4 b4 = __ldg(wb + u);
            accA[4*u+0] = fmaf(xv, t4.x - b4.x, accA[4*u+0]);
            accA[4*u+1] = fmaf(xv, t4.y - b4.y, accA[4*u+1]);
            accA[4*u+2] = fmaf(xv, t4.z - b4.z, accA[4*u+2]);
            accA[4*u+3] = fmaf(xv, t4.w - b4.w, accA[4*u+3]);
            accC[4*u+0] = fmaf(xv, b4.x, accC[4*u+0]);
            accC[4*u+1] = fmaf(xv, b4.y, accC[4*u+1]);
            accC[4*u+2] = fmaf(xv, b4.z, accC[4*u+2]);
            accC[4*u+3] = fmaf(xv, b4.w, accC[4*u+3]);
        }
    }
    size_t rowo = (size_t)(nodeBase + node)*COUT + co;
    #pragma unroll
    for (int s = 0; s < STRIP; s++) {
        g_A[rowo + s] = accA[s] + bias[co + s];
        g_C[rowo + s] = accC[s];
    }
}

// ---------------- gather-max aggregate: out = A[i] + max_k C[knn(i,k)] ----------------
template<int COUT, int CATOFF>
__global__ void agg_kernel() {
    const int node = blockIdx.x;
    const int c = threadIdx.x;
    __shared__ int sidx[KK];
    if (c < KK) sidx[c] = g_knn[(size_t)node*KK + c];
    __syncthreads();
    const int jb = (node >> 12) << 12;   // batch base (NN = 4096)
    float m = -3.4e38f;
    #pragma unroll
    for (int k = 0; k < KK; k++)
        m = fmaxf(m, g_C[(size_t)(jb + sidx[k])*COUT + c]);
    g_xcat[(size_t)node*512 + CATOFF + c] = g_A[(size_t)node*COUT + c] + m;
}

// ---------------- final GEMM [BN,512]x[512,1024] fused with max over N ----------------
__global__ void __launch_bounds__(256) final_kernel(const float* __restrict__ Wf1,
                                                    const float* __restrict__ bf1) {
    __shared__ float As[16][132];   // [k][node]
    __shared__ float Bs[16][132];   // [k][out]
    __shared__ int cmax[128];

    const int tid = threadIdx.x;
    const int nodeBase = blockIdx.x * 128;
    const int outBase  = blockIdx.y * 128;
    const int rb = (tid >> 4) * 8;
    const int cb = (tid & 15) * 8;

    float acc[8][8];
    #pragma unroll
    for (int u = 0; u < 8; u++)
        #pragma unroll
        for (int v = 0; v < 8; v++) acc[u][v] = 0.f;

    for (int kc = 0; kc < 512; kc += 16) {
        __syncthreads();
        for (int e = tid; e < 128*16; e += 256) {
            int node = e >> 4, k = e & 15;
            As[k][node] = g_xcat[(size_t)(nodeBase + node)*512 + kc + k];
        }
        for (int e = tid; e < 16*128; e += 256) {
            int k = e >> 7, o = e & 127;
            Bs[k][o] = Wf1[(size_t)(kc + k)*1024 + outBase + o];
        }
        __syncthreads();
        #pragma unroll
        for (int k = 0; k < 16; k++) {
            float4 a0 = *reinterpret_cast<const float4*>(&As[k][rb]);
            float4 a1 = *reinterpret_cast<const float4*>(&As[k][rb+4]);
            float4 b0 = *reinterpret_cast<const float4*>(&Bs[k][cb]);
            float4 b1 = *reinterpret_cast<const float4*>(&Bs[k][cb+4]);
            float av[8] = {a0.x,a0.y,a0.z,a0.w,a1.x,a1.y,a1.z,a1.w};
            float bv[8] = {b0.x,b0.y,b0.z,b0.w,b1.x,b1.y,b1.z,b1.w};
            #pragma unroll
            for (int u = 0; u < 8; u++)
                #pragma unroll
                for (int v = 0; v < 8; v++) acc[u][v] = fmaf(av[u], bv[v], acc[u][v]);
        }
    }

    if (tid < 128) cmax[tid] = ENC_NEG_INF;
    __syncthreads();

    const int b = nodeBase >> 12;
    #pragma unroll
    for (int v = 0; v < 8; v++) {
        float colm = -3.4e38f;
        #pragma unroll
        for (int u = 0; u < 8; u++) colm = fmaxf(colm, acc[u][v]);
        colm += bf1[outBase + cb + v];
        atomicMax(&cmax[cb + v], encf(colm));
    }
    __syncthreads();
    if (tid < 128) atomicMax(&g_pool_enc[b*1024 + outBase + tid], cmax[tid]);
}

// ---------------- head ----------------
__global__ void head1_kernel(const float* __restrict__ Wa, const float* __restrict__ ba) {
    const int b = blockIdx.x, o = threadIdx.x;   // 512 threads
    __shared__ float p[1024];
    for (int e = o; e < 1024; e += 512) p[e] = decf(g_pool_enc[b*1024 + e]);
    __syncthreads();
    float acc = ba[o];
    #pragma unroll 8
    for (int in = 0; in < 1024; in++) acc = fmaf(p[in], Wa[(size_t)in*512 + o], acc);
    g_h1[b*512 + o] = fmaxf(acc, 0.f);
}

__global__ void head2_kernel(const float* __restrict__ Wb, const float* __restrict__ bb) {
    const int b = blockIdx.x, o = threadIdx.x;   // 256 threads
    __shared__ float p[512];
    for (int e = o; e < 512; e += 256) p[e] = g_h1[b*512 + e];
    __syncthreads();
    float acc = bb[o];
    #pragma unroll 8
    for (int in = 0; in < 512; in++) acc = fmaf(p[in], Wb[(size_t)in*256 + o], acc);
    g_h2[b*256 + o] = fmaxf(acc, 0.f);
}

__global__ void head3_kernel(const float* __restrict__ Wc, const float* __restrict__ bc,
                             float* __restrict__ out) {
    const int b = blockIdx.x, t = threadIdx.x;   // 32 threads
    __shared__ float h[256];
    for (int e = t; e < 256; e += 32) h[e] = g_h2[b*256 + e];
    __syncthreads();
    float logit = -3.4e38f;
    if (t < 23) {
        logit = bc[t];
        #pragma unroll 8
        for (int in = 0; in < 256; in++) logit = fmaf(h[in], Wc[in*23 + t], logit);
    }
    float mx = logit;
    #pragma unroll
    for (int off = 16; off > 0; off >>= 1) mx = fmaxf(mx, __shfl_xor_sync(0xffffffffu, mx, off));
    float ex = (t < 23) ? expf(logit - mx) : 0.f;
    float s = ex;
    #pragma unroll
    for (int off = 16; off > 0; off >>= 1) s += __shfl_xor_sync(0xffffffffu, s, off);
    if (t < 23) out[b*23 + t] = logit - mx - logf(s);
}

// ---------------- launch ----------------
extern "C" void kernel_launch(void* const* d_in, const int* in_sizes, int n_in,
                              void* d_out, int out_size) {
    const float* pos = (const float*)d_in[0];
    const float* x   = (const float*)d_in[1];
    const float* W1  = (const float*)d_in[2];  const float* b1 = (const float*)d_in[3];
    const float* W2  = (const float*)d_in[4];  const float* b2 = (const float*)d_in[5];
    const float* W3  = (const float*)d_in[6];  const float* b3 = (const float*)d_in[7];
    const float* W4  = (const float*)d_in[8];  const float* b4 = (const float*)d_in[9];
    const float* Wf1 = (const float*)d_in[10]; const float* bf1 = (const float*)d_in[11];
    const float* Wa  = (const float*)d_in[12]; const float* ba = (const float*)d_in[13];
    const float* Wb  = (const float*)d_in[14]; const float* bb = (const float*)d_in[15];
    const float* Wc  = (const float*)d_in[16]; const float* bc = (const float*)d_in[17];
    float* out = (float*)d_out;

    // allow >48KB dynamic smem where needed (host-side config, not a stream op;
    // legal during graph capture and idempotent across calls)
    cudaFuncSetAttribute(knn_kernel<6,   6,   true,  0>,   cudaFuncAttributeMaxDynamicSharedMemorySize, knn_smem_bytes<6>());
    cudaFuncSetAttribute(knn_kernel<64,  512, false, 0>,   cudaFuncAttributeMaxDynamicSharedMemorySize, knn_smem_bytes<64>());
    cudaFuncSetAttribute(knn_kernel<64,  512, false, 64>,  cudaFuncAttributeMaxDynamicSharedMemorySize, knn_smem_bytes<64>());
    cudaFuncSetAttribute(knn_kernel<128, 512, false, 128>, cudaFuncAttributeMaxDynamicSharedMemorySize, knn_smem_bytes<128>());

    build_x0_kernel<<<(BN*6 + 255)/256, 256>>>(pos, x);
    init_pool_kernel<<<(BB*1024 + 255)/256, 256>>>();

    // layer 1: x0 (CIN=6, stride 6) -> x1 (64) @ cat offset 0
    sq_kernel<6, 6, true, 0><<<BN/256, 256>>>();
    knn_kernel<6, 6, true, 0><<<dim3(NN/64, BB), 256, knn_smem_bytes<6>()>>>();
    proj_kernel<6, 6, true, 0, 64><<<BN/16, 256>>>(W1, b1);
    agg_kernel<64, 0><<<BN, 64>>>();

    // layer 2: x1 (CIN=64, stride 512, off 0) -> x2 (64) @ cat offset 64
    sq_kernel<64, 512, false, 0><<<BN/256, 256>>>();
    knn_kernel<64, 512, false, 0><<<dim3(NN/64, BB), 256, knn_smem_bytes<64>()>>>();
    proj_kernel<64, 512, false, 0, 64><<<BN/16, 256>>>(W2, b2);
    agg_kernel<64, 64><<<BN, 64>>>();

    // layer 3: x2 (CIN=64, off 64) -> x3 (128) @ cat offset 128
    sq_kernel<64, 512, false, 64><<<BN/256, 256>>>();
    knn_kernel<64, 512, false, 64><<<dim3(NN/64, BB), 256, knn_smem_bytes<64>()>>>();
    proj_kernel<64, 512, false, 64, 128><<<BN/16, 256>>>(W3, b3);
    agg_kernel<128, 128><<<BN, 128>>>();

    // layer 4: x3 (CIN=128, off 128) -> x4 (256) @ cat offset 256
    sq_kernel<128, 512, false, 128><<<BN/256, 256>>>();
    knn_kernel<128, 512, false, 128><<<dim3(NN/64, BB), 256, knn_smem_bytes<128>()>>>();
    proj_kernel<128, 512, false, 128, 256><<<BN/16, 256>>>(W4, b4);
    agg_kernel<256, 256><<<BN, 256>>>();

    // final feature GEMM + global max-pool
    final_kernel<<<dim3(BN/128, 1024/128), 256>>>(Wf1, bf1);

    // head
    head1_kernel<<<BB, 512>>>(Wa, ba);
    head2_kernel<<<BB, 256>>>(Wb, bb);
    head3_kernel<<<BB, 32>>>(Wc, bc, out);
}

// round 12
// speedup vs baseline: 1.0608x; 1.0375x over previous
#include <cuda_runtime.h>
#include <math.h>

#define BB 8
#define NN 4096
#define KK 20
#define BN (BB*NN)

// ---------------- scratch (static device globals; no runtime alloc) ----------------
__device__ float g_x0[BN*6];
__device__ float g_xcat[(size_t)BN*512];
__device__ float g_A[(size_t)BN*256];
__device__ float g_C[(size_t)BN*256];
__device__ float g_sq[BN];
__device__ int   g_knn[BN*KK];
__device__ int   g_pool_enc[BB*1024];
__device__ float g_h1[BB*512];
__device__ float g_h2[BB*256];

__device__ __forceinline__ int   encf(float f){ int i=__float_as_int(f); return i>=0 ? i : i^0x7FFFFFFF; }
__device__ __forceinline__ float decf(int i){ return __int_as_float(i>=0 ? i : i^0x7FFFFFFF); }
#define ENC_NEG_INF (-2139095041)  /* encf(-inf) = 0x807FFFFF */

// ---------------- build x0 = concat(pos, x) ----------------
__global__ void build_x0_kernel(const float* __restrict__ pos, const float* __restrict__ x) {
    int g = blockIdx.x * 256 + threadIdx.x;
    if (g >= BN*6) return;
    int n = g / 6, c = g - n*6;
    g_x0[g] = (c < 3) ? pos[n*3 + c] : x[n*3 + c - 3];
}

__global__ void init_pool_kernel() {
    int g = blockIdx.x * 256 + threadIdx.x;
    if (g < BB*1024) g_pool_enc[g] = ENC_NEG_INF;
}

// ---------------- squared norms ----------------
template<int CIN, int SIN, bool USE_X0, int INOFF>
__global__ void sq_kernel() {
    int g = blockIdx.x * 256 + threadIdx.x;
    if (g >= BN) return;
    const float* base = USE_X0 ? g_x0 : (g_xcat + INOFF);
    const float* xr = base + (size_t)g * SIN;
    float s = 0.f;
    #pragma unroll 8
    for (int c = 0; c < CIN; c++) { float v = xr[c]; s += v*v; }
    g_sq[g] = s;
}

// ---------------- kNN: 4-way j-split, PACKED-KEY register top-20 ----------------
// 64 nodes/block x 4 splits = 256 threads; the 4 splits of a node are adjacent
// lanes of one warp. Candidate key packs rank info into ONE int:
//   key = (orderable(r2) & ~0xFFF) | j     (r2 = sqj - 2*dot; j < 4096)
// so the top-20 is 20 registers and each insert step is exactly two IMNMX
// (min/max) ALU ops — no predicates, no index selects. Ties in the truncated
// distance order by lower j, matching top_k tie-breaking. Splits share a
// pruning threshold (min of per-split 20th keys) via 2 shfl.xor per tile.
// Merge: splits 1..3 publish sorted key lists; split 0 folds (early exit).
template<int CIN> __host__ __device__ constexpr int knn_xis_stride() { return CIN + 4; }
template<int CIN> __host__ __device__ constexpr int knn_xj_stride()  { return 16*CIN + 8; }
template<int CIN> __host__ __device__ constexpr int knn_xj_region()  {
    return (4*knn_xj_stride<CIN>() > 192*KK) ? 4*knn_xj_stride<CIN>() : 192*KK;
}
template<int CIN> __host__ __device__ constexpr int knn_smem_bytes() {
    return (64*knn_xis_stride<CIN>() + knn_xj_region<CIN>()) * 4;
}

template<int CIN, int SIN, bool USE_X0, int INOFF>
__global__ void __launch_bounds__(256, 2) knn_kernel() {
    constexpr int TI = 64, SPLIT = 4, TJ = 16;
    constexpr int JSEG = NN / SPLIT;                 // 1024
    constexpr int XIS_STRIDE = knn_xis_stride<CIN>();
    constexpr int XJ_STRIDE  = knn_xj_stride<CIN>();

    extern __shared__ float smem[];
    float* Xis = smem;                               // TI * XIS_STRIDE
    float* Xjs = smem + TI*XIS_STRIDE;               // XJ region (reused for merge)
    __shared__ float sqj_s[SPLIT*TJ];

    const int b   = blockIdx.y;
    const int tid = threadIdx.x;
    const int nl  = tid >> 2;        // node-local 0..63
    const int sp  = tid & 3;         // split 0..3
    const int i   = blockIdx.x*TI + nl;
    const float* base = USE_X0 ? g_x0 : (g_xcat + INOFF);
    const float* Xb = base + (size_t)b * NN * SIN;

    // stage this block's 64 xi rows (coalesced; synced by first loop barrier)
    for (int e = tid; e < TI*CIN; e += 256) {
        int r = e / CIN, c = e - r*CIN;
        Xis[r*XIS_STRIDE + c] = Xb[(size_t)(blockIdx.x*TI + r)*SIN + c];
    }

    // top-20 packed keys (sorted ascending), register resident
    int kd[KK];
    #pragma unroll
    for (int k = 0; k < KK; k++) kd[k] = 0x7FFFFFFF;
    int thr = 0x7FFFFFFF;            // shared (min over splits) pruning bound

    const int jbase = sp * JSEG;
    const float* xi = Xis + nl*XIS_STRIDE;
    const float* xj = Xjs + sp*XJ_STRIDE;

    for (int jo = 0; jo < JSEG; jo += TJ) {
        __syncthreads();
        // stage all 4 splits' j-tiles (4*TJ*CIN floats, coalesced)
        for (int e = tid; e < SPLIT*TJ*CIN; e += 256) {
            int s = e / (TJ*CIN);
            int rem = e - s*(TJ*CIN);
            int r = rem / CIN, c = rem - r*CIN;
            Xjs[s*XJ_STRIDE + r*CIN + c] = Xb[(size_t)(s*JSEG + jo + r)*SIN + c];
        }
        if (tid < SPLIT*TJ)
            sqj_s[tid] = g_sq[b*NN + (tid>>4)*JSEG + jo + (tid&15)];
        __syncthreads();

        float acc[TJ];
        #pragma unroll
        for (int j = 0; j < TJ; j++) acc[j] = 0.f;

        if (CIN % 4 == 0) {
            #pragma unroll 4
            for (int c4 = 0; c4 < CIN/4; c4++) {
                const float a0 = xi[c4*4+0];
                const float a1 = xi[c4*4+1];
                const float a2 = xi[c4*4+2];
                const float a3 = xi[c4*4+3];
                #pragma unroll
                for (int j = 0; j < TJ; j++) {
                    const float4 b4 = *reinterpret_cast<const float4*>(&xj[j*CIN + c4*4]);
                    acc[j] = fmaf(a0, b4.x, acc[j]);
                    acc[j] = fmaf(a1, b4.y, acc[j]);
                    acc[j] = fmaf(a2, b4.z, acc[j]);
                    acc[j] = fmaf(a3, b4.w, acc[j]);
                }
            }
        } else {
            #pragma unroll
            for (int c = 0; c < CIN; c++) {
                const float xv = xi[c];
                #pragma unroll
                for (int j = 0; j < TJ; j++) acc[j] = fmaf(xv, xj[j*CIN + c], acc[j]);
            }
        }

        #pragma unroll
        for (int j = 0; j < TJ; j++) {
            float r2 = fmaf(-2.f, acc[j], sqj_s[sp*TJ + j]);   // dist - sqi (rank-equiv)
            int e = __float_as_int(r2);
            e ^= (int)(((unsigned)(e >> 31)) >> 1);            // orderable int
            int key = (e & ~0xFFF) | (jbase + jo + j);         // 20b dist | 12b index
            if (key < thr) {
                int cd = key;
                #pragma unroll
                for (int k = 0; k < KK; k++) {
                    const int lo = min(kd[k], cd);
                    const int hi = max(kd[k], cd);
                    kd[k] = lo; cd = hi;                        // 2x IMNMX per step
                }
            }
        }

        // exchange pruning bound across the node's 4 splits (same warp, adjacent lanes)
        {
            int w = kd[KK-1];
            w = min(w, __shfl_xor_sync(0xffffffffu, w, 1));
            w = min(w, __shfl_xor_sync(0xffffffffu, w, 2));
            thr = w;
        }
    }

    // ---- merge: splits 1..3 publish sorted key lists; split 0 folds them in ----
    __syncthreads();                         // main-loop reads of Xjs done
    int* md = (int*)Xjs;
    if (sp != 0) {
        const int o = (nl*3 + (sp-1))*KK;
        #pragma unroll
        for (int k = 0; k < KK; k++) md[o+k] = kd[k];
    }
    __syncthreads();
    if (sp == 0) {
        int worst = kd[KK-1];
        #pragma unroll
        for (int s = 0; s < 3; s++) {
            const int o = (nl*3 + s)*KK;
            for (int k = 0; k < KK; k++) {
                int cd = md[o+k];
                if (cd >= worst) break;      // source list sorted ascending
                #pragma unroll
                for (int kk = 0; kk < KK; kk++) {
                    const int lo = min(kd[kk], cd);
                    const int hi = max(kd[kk], cd);
                    kd[kk] = lo; cd = hi;
                }
                worst = kd[KK-1];
            }
        }
        int* dst = g_knn + (size_t)(b*NN + i)*KK;
        #pragma unroll
        for (int k = 0; k < KK; k++) dst[k] = kd[k] & 0xFFF;
    }
}

// ---------------- per-node projections: A = X(Wt-Wb)+b, C = X Wb ----------------
template<int CIN, int SIN, bool USE_X0, int INOFF, int COUT>
__global__ void __launch_bounds__(256) proj_kernel(const float* __restrict__ W,
                                                   const float* __restrict__ bias) {
    constexpr int TM = 16;
    constexpr int STRIP = COUT / 16;        // 4, 8, or 16 (all %4==0)
    __shared__ float xs[TM][CIN];

    const int nodeBase = blockIdx.x * TM;
    const int tid = threadIdx.x;
    const float* base = USE_X0 ? g_x0 : (g_xcat + INOFF);

    for (int e = tid; e < TM*CIN; e += 256) {
        int r = e / CIN, c = e - r*CIN;
        xs[r][c] = base[(size_t)(nodeBase + r)*SIN + c];
    }
    __syncthreads();

    const int node = tid >> 4;
    const int cg   = tid & 15;
    const int co   = cg * STRIP;

    float accA[STRIP], accC[STRIP];
    #pragma unroll
    for (int s = 0; s < STRIP; s++) { accA[s] = 0.f; accC[s] = 0.f; }

    #pragma unroll 4
    for (int c = 0; c < CIN; c++) {
        float xv = xs[node][c];
        const float4* wt = reinterpret_cast<const float4*>(W + (size_t)c*COUT + co);
        const float4* wb = reinterpret_cast<const float4*>(W + (size_t)(CIN + c)*COUT + co);
        #pragma unroll
        for (int u = 0; u < STRIP/4; u++) {
            float4 t4 = __ldg(wt + u);
            float4 b4 = __ldg(wb + u);
            accA[4*u+0] = fmaf(xv, t4.x - b4.x, accA[4*u+0]);
            accA[4*u+1] = fmaf(xv, t4.y - b4.y, accA[4*u+1]);
            accA[4*u+2] = fmaf(xv, t4.z - b4.z, accA[4*u+2]);
            accA[4*u+3] = fmaf(xv, t4.w - b4.w, accA[4*u+3]);
            accC[4*u+0] = fmaf(xv, b4.x, accC[4*u+0]);
            accC[4*u+1] = fmaf(xv, b4.y, accC[4*u+1]);
            accC[4*u+2] = fmaf(xv, b4.z, accC[4*u+2]);
            accC[4*u+3] = fmaf(xv, b4.w, accC[4*u+3]);
        }
    }
    size_t rowo = (size_t)(nodeBase + node)*COUT + co;
    #pragma unroll
    for (int s = 0; s < STRIP; s++) {
        g_A[rowo + s] = accA[s] + bias[co + s];
        g_C[rowo + s] = accC[s];
    }
}

// ---------------- gather-max aggregate: out = A[i] + max_k C[knn(i,k)] ----------------
template<int COUT, int CATOFF>
__global__ void agg_kernel() {
    const int node = blockIdx.x;
    const int c = threadIdx.x;
    __shared__ int sidx[KK];
    if (c < KK) sidx[c] = g_knn[(size_t)node*KK + c];
    __syncthreads();
    const int jb = (node >> 12) << 12;   // batch base (NN = 4096)
    float m = -3.4e38f;
    #pragma unroll
    for (int k = 0; k < KK; k++)
        m = fmaxf(m, g_C[(size_t)(jb + sidx[k])*COUT + c]);
    g_xcat[(size_t)node*512 + CATOFF + c] = g_A[(size_t)node*COUT + c] + m;
}

// ---------------- final GEMM [BN,512]x[512,1024] fused with max over N ----------------
__global__ void __launch_bounds__(256) final_kernel(const float* __restrict__ Wf1,
                                                    const float* __restrict__ bf1) {
    __shared__ float As[16][132];   // [k][node]
    __shared__ float Bs[16][132];   // [k][out]
    __shared__ int cmax[128];

    const int tid = threadIdx.x;
    const int nodeBase = blockIdx.x * 128;
    const int outBase  = blockIdx.y * 128;
    const int rb = (tid >> 4) * 8;
    const int cb = (tid & 15) * 8;

    float acc[8][8];
    #pragma unroll
    for (int u = 0; u < 8; u++)
        #pragma unroll
        for (int v = 0; v < 8; v++) acc[u][v] = 0.f;

    for (int kc = 0; kc < 512; kc += 16) {
        __syncthreads();
        for (int e = tid; e < 128*16; e += 256) {
            int node = e >> 4, k = e & 15;
            As[k][node] = g_xcat[(size_t)(nodeBase + node)*512 + kc + k];
        }
        for (int e = tid; e < 16*128; e += 256) {
            int k = e >> 7, o = e & 127;
            Bs[k][o] = Wf1[(size_t)(kc + k)*1024 + outBase + o];
        }
        __syncthreads();
        #pragma unroll
        for (int k = 0; k < 16; k++) {
            float4 a0 = *reinterpret_cast<const float4*>(&As[k][rb]);
            float4 a1 = *reinterpret_cast<const float4*>(&As[k][rb+4]);
            float4 b0 = *reinterpret_cast<const float4*>(&Bs[k][cb]);
            float4 b1 = *reinterpret_cast<const float4*>(&Bs[k][cb+4]);
            float av[8] = {a0.x,a0.y,a0.z,a0.w,a1.x,a1.y,a1.z,a1.w};
            float bv[8] = {b0.x,b0.y,b0.z,b0.w,b1.x,b1.y,b1.z,b1.w};
            #pragma unroll
            for (int u = 0; u < 8; u++)
                #pragma unroll
                for (int v = 0; v < 8; v++) acc[u][v] = fmaf(av[u], bv[v], acc[u][v]);
        }
    }

    if (tid < 128) cmax[tid] = ENC_NEG_INF;
    __syncthreads();

    const int b = nodeBase >> 12;
    #pragma unroll
    for (int v = 0; v < 8; v++) {
        float colm = -3.4e38f;
        #pragma unroll
        for (int u = 0; u < 8; u++) colm = fmaxf(colm, acc[u][v]);
        colm += bf1[outBase + cb + v];
        atomicMax(&cmax[cb + v], encf(colm));
    }
    __syncthreads();
    if (tid < 128) atomicMax(&g_pool_enc[b*1024 + outBase + tid], cmax[tid]);
}

// ---------------- head ----------------
__global__ void head1_kernel(const float* __restrict__ Wa, const float* __restrict__ ba) {
    const int b = blockIdx.x, o = threadIdx.x;   // 512 threads
    __shared__ float p[1024];
    for (int e = o; e < 1024; e += 512) p[e] = decf(g_pool_enc[b*1024 + e]);
    __syncthreads();
    float acc = ba[o];
    #pragma unroll 8
    for (int in = 0; in < 1024; in++) acc = fmaf(p[in], Wa[(size_t)in*512 + o], acc);
    g_h1[b*512 + o] = fmaxf(acc, 0.f);
}

__global__ void head2_kernel(const float* __restrict__ Wb, const float* __restrict__ bb) {
    const int b = blockIdx.x, o = threadIdx.x;   // 256 threads
    __shared__ float p[512];
    for (int e = o; e < 512; e += 256) p[e] = g_h1[b*512 + e];
    __syncthreads();
    float acc = bb[o];
    #pragma unroll 8
    for (int in = 0; in < 512; in++) acc = fmaf(p[in], Wb[(size_t)in*256 + o], acc);
    g_h2[b*256 + o] = fmaxf(acc, 0.f);
}

__global__ void head3_kernel(const float* __restrict__ Wc, const float* __restrict__ bc,
                             float* __restrict__ out) {
    const int b = blockIdx.x, t = threadIdx.x;   // 32 threads
    __shared__ float h[256];
    for (int e = t; e < 256; e += 32) h[e] = g_h2[b*256 + e];
    __syncthreads();
    float logit = -3.4e38f;
    if (t < 23) {
        logit = bc[t];
        #pragma unroll 8
        for (int in = 0; in < 256; in++) logit = fmaf(h[in], Wc[in*23 + t], logit);
    }
    float mx = logit;
    #pragma unroll
    for (int off = 16; off > 0; off >>= 1) mx = fmaxf(mx, __shfl_xor_sync(0xffffffffu, mx, off));
    float ex = (t < 23) ? expf(logit - mx) : 0.f;
    float s = ex;
    #pragma unroll
    for (int off = 16; off > 0; off >>= 1) s += __shfl_xor_sync(0xffffffffu, s, off);
    if (t < 23) out[b*23 + t] = logit - mx - logf(s);
}

// ---------------- launch ----------------
extern "C" void kernel_launch(void* const* d_in, const int* in_sizes, int n_in,
                              void* d_out, int out_size) {
    const float* pos = (const float*)d_in[0];
    const float* x   = (const float*)d_in[1];
    const float* W1  = (const float*)d_in[2];  const float* b1 = (const float*)d_in[3];
    const float* W2  = (const float*)d_in[4];  const float* b2 = (const float*)d_in[5];
    const float* W3  = (const float*)d_in[6];  const float* b3 = (const float*)d_in[7];
    const float* W4  = (const float*)d_in[8];  const float* b4 = (const float*)d_in[9];
    const float* Wf1 = (const float*)d_in[10]; const float* bf1 = (const float*)d_in[11];
    const float* Wa  = (const float*)d_in[12]; const float* ba = (const float*)d_in[13];
    const float* Wb  = (const float*)d_in[14]; const float* bb = (const float*)d_in[15];
    const float* Wc  = (const float*)d_in[16]; const float* bc = (const float*)d_in[17];
    float* out = (float*)d_out;

    // allow >48KB dynamic smem where needed (host-side config, not a stream op;
    // legal during graph capture and idempotent across calls)
    cudaFuncSetAttribute(knn_kernel<6,   6,   true,  0>,   cudaFuncAttributeMaxDynamicSharedMemorySize, knn_smem_bytes<6>());
    cudaFuncSetAttribute(knn_kernel<64,  512, false, 0>,   cudaFuncAttributeMaxDynamicSharedMemorySize, knn_smem_bytes<64>());
    cudaFuncSetAttribute(knn_kernel<64,  512, false, 64>,  cudaFuncAttributeMaxDynamicSharedMemorySize, knn_smem_bytes<64>());
    cudaFuncSetAttribute(knn_kernel<128, 512, false, 128>, cudaFuncAttributeMaxDynamicSharedMemorySize, knn_smem_bytes<128>());

    build_x0_kernel<<<(BN*6 + 255)/256, 256>>>(pos, x);
    init_pool_kernel<<<(BB*1024 + 255)/256, 256>>>();

    // layer 1: x0 (CIN=6, stride 6) -> x1 (64) @ cat offset 0
    sq_kernel<6, 6, true, 0><<<BN/256, 256>>>();
    knn_kernel<6, 6, true, 0><<<dim3(NN/64, BB), 256, knn_smem_bytes<6>()>>>();
    proj_kernel<6, 6, true, 0, 64><<<BN/16, 256>>>(W1, b1);
    agg_kernel<64, 0><<<BN, 64>>>();

    // layer 2: x1 (CIN=64, stride 512, off 0) -> x2 (64) @ cat offset 64
    sq_kernel<64, 512, false, 0><<<BN/256, 256>>>();
    knn_kernel<64, 512, false, 0><<<dim3(NN/64, BB), 256, knn_smem_bytes<64>()>>>();
    proj_kernel<64, 512, false, 0, 64><<<BN/16, 256>>>(W2, b2);
    agg_kernel<64, 64><<<BN, 64>>>();

    // layer 3: x2 (CIN=64, off 64) -> x3 (128) @ cat offset 128
    sq_kernel<64, 512, false, 64><<<BN/256, 256>>>();
    knn_kernel<64, 512, false, 64><<<dim3(NN/64, BB), 256, knn_smem_bytes<64>()>>>();
    proj_kernel<64, 512, false, 64, 128><<<BN/16, 256>>>(W3, b3);
    agg_kernel<128, 128><<<BN, 128>>>();

    // layer 4: x3 (CIN=128, off 128) -> x4 (256) @ cat offset 256
    sq_kernel<128, 512, false, 128><<<BN/256, 256>>>();
    knn_kernel<128, 512, false, 128><<<dim3(NN/64, BB), 256, knn_smem_bytes<128>()>>>();
    proj_kernel<128, 512, false, 128, 256><<<BN/16, 256>>>(W4, b4);
    agg_kernel<256, 256><<<BN, 256>>>();

    // final feature GEMM + global max-pool
    final_kernel<<<dim3(BN/128, 1024/128), 256>>>(Wf1, bf1);

    // head
    head1_kernel<<<BB, 512>>>(Wa, ba);
    head2_kernel<<<BB, 256>>>(Wb, bb);
    head3_kernel<<<BB, 32>>>(Wc, bc, out);
}

// round 13
// speedup vs baseline: 1.5395x; 1.4512x over previous
#include <cuda_runtime.h>
#include <math.h>

#define BB 8
#define NN 4096
#define KK 20
#define BN (BB*NN)

// ---------------- scratch (static device globals; no runtime alloc) ----------------
__device__ float g_x0[BN*6];
__device__ float g_xcat[(size_t)BN*512];
__device__ float g_A[(size_t)BN*256];
__device__ float g_C[(size_t)BN*256];
__device__ float g_sq[BN];
__device__ int   g_knn[BN*KK];
__device__ int   g_pool_enc[BB*1024];
__device__ float g_h1[BB*512];
__device__ float g_h2[BB*256];

__device__ __forceinline__ int   encf(float f){ int i=__float_as_int(f); return i>=0 ? i : i^0x7FFFFFFF; }
__device__ __forceinline__ float decf(int i){ return __int_as_float(i>=0 ? i : i^0x7FFFFFFF); }
#define ENC_NEG_INF (-2139095041)  /* encf(-inf) = 0x807FFFFF */

// ---------------- build x0 = concat(pos, x) ----------------
__global__ void build_x0_kernel(const float* __restrict__ pos, const float* __restrict__ x) {
    int g = blockIdx.x * 256 + threadIdx.x;
    if (g >= BN*6) return;
    int n = g / 6, c = g - n*6;
    g_x0[g] = (c < 3) ? pos[n*3 + c] : x[n*3 + c - 3];
}

__global__ void init_pool_kernel() {
    int g = blockIdx.x * 256 + threadIdx.x;
    if (g < BB*1024) g_pool_enc[g] = ENC_NEG_INF;
}

// ---------------- squared norms ----------------
template<int CIN, int SIN, bool USE_X0, int INOFF>
__global__ void sq_kernel() {
    int g = blockIdx.x * 256 + threadIdx.x;
    if (g >= BN) return;
    const float* base = USE_X0 ? g_x0 : (g_xcat + INOFF);
    const float* xr = base + (size_t)g * SIN;
    float s = 0.f;
    #pragma unroll 8
    for (int c = 0; c < CIN; c++) { float v = xr[c]; s += v*v; }
    g_sq[g] = s;
}

// ---------------- kNN: 4-nodes-per-thread register-blocked gram + packed-key top-20 ----
// 64 threads/block; thread (quad=tid>>2, sp=tid&3) owns nodes {quad+16n} (n=0..3)
// and scans split sp's j-range in 8-wide tiles. Register blocking the i-dim means
// each xj LDS.128 feeds 4 nodes (16 FMA) -> ~1.5 B/FMA, turning the kernel from
// smem-crossbar-bound into FFMA-bound. Top-20 kept as packed keys
// (orderable(r2)&~0xFFF | j) with 2-IMNMX insert steps; per-node pruning
// thresholds exchanged across a node's 4 splits via shfl.xor each tile.
// Bank layout: XJ_STRIDE=8*CIN+4 puts the 4 splits on distinct bank quads
// (broadcast within a split-group); XIS_STRIDE=CIN+4 with strided node
// assignment puts the 8 quads of a warp on 8 distinct bank positions.
template<int CIN> __host__ __device__ constexpr int knn_xis_stride() { return CIN + 4; }
template<int CIN> __host__ __device__ constexpr int knn_xj_stride()  { return 8*CIN + 4; }
template<int CIN> __host__ __device__ constexpr int knn_xj_region()  {
    return (4*knn_xj_stride<CIN>() > 192*KK) ? 4*knn_xj_stride<CIN>() : 192*KK;
}
template<int CIN> __host__ __device__ constexpr int knn_smem_bytes() {
    return (64*knn_xis_stride<CIN>() + knn_xj_region<CIN>()) * 4;
}

template<int CIN, int SIN, bool USE_X0, int INOFF>
__global__ void __launch_bounds__(64, 4) knn_kernel() {
    constexpr int TI = 64, SPLIT = 4, TJ = 8, RN = 4;
    constexpr int JSEG = NN / SPLIT;                 // 1024
    constexpr int XIS_STRIDE = knn_xis_stride<CIN>();
    constexpr int XJ_STRIDE  = knn_xj_stride<CIN>();

    extern __shared__ float smem[];
    float* Xis = smem;                               // TI * XIS_STRIDE
    float* Xjs = smem + TI*XIS_STRIDE;               // XJ region (reused for merge)
    __shared__ float sqj_s[SPLIT*TJ];

    const int b    = blockIdx.y;
    const int tid  = threadIdx.x;
    const int quad = tid >> 2;       // 0..15
    const int sp   = tid & 3;        // split 0..3
    const float* base = USE_X0 ? g_x0 : (g_xcat + INOFF);
    const float* Xb = base + (size_t)b * NN * SIN;

    // stage this block's 64 xi rows (coalesced; synced by first loop barrier)
    if (CIN % 4 == 0) {
        for (int e = tid; e < TI*(CIN/4); e += 64) {
            int r = e / (CIN/4), c4 = e - r*(CIN/4);     // CIN/4 pow2 -> shifts
            float4 v = *reinterpret_cast<const float4*>(&Xb[(size_t)(blockIdx.x*TI + r)*SIN + c4*4]);
            *reinterpret_cast<float4*>(&Xis[r*XIS_STRIDE + c4*4]) = v;
        }
    } else {
        for (int e = tid; e < TI*CIN; e += 64) {
            int r = e / CIN, c = e - r*CIN;
            Xis[r*XIS_STRIDE + c] = Xb[(size_t)(blockIdx.x*TI + r)*SIN + c];
        }
    }

    // per-node packed-key top-20 lists (sorted ascending), register resident
    int kd[RN][KK];
    #pragma unroll
    for (int n = 0; n < RN; n++)
        #pragma unroll
        for (int k = 0; k < KK; k++) kd[n][k] = 0x7FFFFFFF;
    int thr[RN];
    #pragma unroll
    for (int n = 0; n < RN; n++) thr[n] = 0x7FFFFFFF;

    const int jbase = sp * JSEG;
    const float* xj = Xjs + sp*XJ_STRIDE;

    for (int jo = 0; jo < JSEG; jo += TJ) {
        __syncthreads();
        // stage all 4 splits' 8-row j-tiles
        if (CIN % 4 == 0) {
            for (int e = tid; e < SPLIT*TJ*(CIN/4); e += 64) {
                int s = e / (TJ*(CIN/4));                 // TJ*CIN/4 pow2
                int rem = e - s*(TJ*(CIN/4));
                int r = rem / (CIN/4), c4 = rem - r*(CIN/4);
                float4 v = *reinterpret_cast<const float4*>(&Xb[(size_t)(s*JSEG + jo + r)*SIN + c4*4]);
                *reinterpret_cast<float4*>(&Xjs[s*XJ_STRIDE + r*CIN + c4*4]) = v;
            }
        } else {
            for (int e = tid; e < SPLIT*TJ*CIN; e += 64) {
                int s = e / (TJ*CIN);
                int rem = e - s*(TJ*CIN);
                int r = rem / CIN, c = rem - r*CIN;
                Xjs[s*XJ_STRIDE + r*CIN + c] = Xb[(size_t)(s*JSEG + jo + r)*SIN + c];
            }
        }
        if (tid < SPLIT*TJ)
            sqj_s[tid] = g_sq[b*NN + (tid>>3)*JSEG + jo + (tid&7)];
        __syncthreads();

        float acc[RN][TJ];
        #pragma unroll
        for (int n = 0; n < RN; n++)
            #pragma unroll
            for (int j = 0; j < TJ; j++) acc[n][j] = 0.f;

        if (CIN % 4 == 0) {
            #pragma unroll 4
            for (int c4 = 0; c4 < CIN/4; c4++) {
                float4 A[RN];
                #pragma unroll
                for (int n = 0; n < RN; n++)
                    A[n] = *reinterpret_cast<const float4*>(&Xis[(quad + 16*n)*XIS_STRIDE + c4*4]);
                #pragma unroll
                for (int j = 0; j < TJ; j++) {
                    const float4 b4 = *reinterpret_cast<const float4*>(&xj[j*CIN + c4*4]);
                    #pragma unroll
                    for (int n = 0; n < RN; n++) {
                        acc[n][j] = fmaf(A[n].x, b4.x, acc[n][j]);
                        acc[n][j] = fmaf(A[n].y, b4.y, acc[n][j]);
                        acc[n][j] = fmaf(A[n].z, b4.z, acc[n][j]);
                        acc[n][j] = fmaf(A[n].w, b4.w, acc[n][j]);
                    }
                }
            }
        } else {
            #pragma unroll
            for (int c = 0; c < CIN; c++) {
                float a[RN];
                #pragma unroll
                for (int n = 0; n < RN; n++) a[n] = Xis[(quad + 16*n)*XIS_STRIDE + c];
                #pragma unroll
                for (int j = 0; j < TJ; j++) {
                    const float bv = xj[j*CIN + c];
                    #pragma unroll
                    for (int n = 0; n < RN; n++) acc[n][j] = fmaf(a[n], bv, acc[n][j]);
                }
            }
        }

        #pragma unroll
        for (int j = 0; j < TJ; j++) {
            const float sj = sqj_s[sp*TJ + j];
            const int jidx = jbase + jo + j;
            #pragma unroll
            for (int n = 0; n < RN; n++) {
                float r2 = fmaf(-2.f, acc[n][j], sj);      // dist - sqi (rank-equiv)
                int e = __float_as_int(r2);
                e ^= (int)(((unsigned)(e >> 31)) >> 1);    // orderable int
                int key = (e & ~0xFFF) | jidx;             // 20b dist | 12b index
                if (key < thr[n]) {
                    int cd = key;
                    #pragma unroll
                    for (int k = 0; k < KK; k++) {
                        const int lo = min(kd[n][k], cd);
                        const int hi = max(kd[n][k], cd);
                        kd[n][k] = lo; cd = hi;            // 2x IMNMX per step
                    }
                }
            }
        }

        // per-node pruning bound across the node's 4 splits (adjacent lanes)
        #pragma unroll
        for (int n = 0; n < RN; n++) {
            int w = kd[n][KK-1];
            w = min(w, __shfl_xor_sync(0xffffffffu, w, 1));
            w = min(w, __shfl_xor_sync(0xffffffffu, w, 2));
            thr[n] = w;
        }
    }

    // ---- merge: splits 1..3 publish sorted key lists; split 0 folds them in ----
    __syncthreads();                         // main-loop reads of Xjs done
    int* md = (int*)Xjs;
    if (sp != 0) {
        #pragma unroll
        for (int n = 0; n < RN; n++) {
            const int o = ((quad + 16*n)*3 + (sp-1))*KK;
            #pragma unroll
            for (int k = 0; k < KK; k++) md[o+k] = kd[n][k];
        }
    }
    __syncthreads();
    if (sp == 0) {
        #pragma unroll
        for (int n = 0; n < RN; n++) {
            const int nl = quad + 16*n;
            int worst = kd[n][KK-1];
            for (int s = 0; s < 3; s++) {
                const int o = (nl*3 + s)*KK;
                for (int k = 0; k < KK; k++) {
                    int cd = md[o+k];
                    if (cd >= worst) break;  // source list sorted ascending
                    #pragma unroll
                    for (int kk = 0; kk < KK; kk++) {
                        const int lo = min(kd[n][kk], cd);
                        const int hi = max(kd[n][kk], cd);
                        kd[n][kk] = lo; cd = hi;
                    }
                    worst = kd[n][KK-1];
                }
            }
            int* dst = g_knn + (size_t)(b*NN + blockIdx.x*TI + nl)*KK;
            #pragma unroll
            for (int k = 0; k < KK; k++) dst[k] = kd[n][k] & 0xFFF;
        }
    }
}

// ---------------- per-node projections: A = X(Wt-Wb)+b, C = X Wb ----------------
template<int CIN, int SIN, bool USE_X0, int INOFF, int COUT>
__global__ void __launch_bounds__(256) proj_kernel(const float* __restrict__ W,
                                                   const float* __restrict__ bias) {
    constexpr int TM = 16;
    constexpr int STRIP = COUT / 16;        // 4, 8, or 16 (all %4==0)
    __shared__ float xs[TM][CIN];

    const int nodeBase = blockIdx.x * TM;
    const int tid = threadIdx.x;
    const float* base = USE_X0 ? g_x0 : (g_xcat + INOFF);

    for (int e = tid; e < TM*CIN; e += 256) {
        int r = e / CIN, c = e - r*CIN;
        xs[r][c] = base[(size_t)(nodeBase + r)*SIN + c];
    }
    __syncthreads();

    const int node = tid >> 4;
    const int cg   = tid & 15;
    const int co   = cg * STRIP;

    float accA[STRIP], accC[STRIP];
    #pragma unroll
    for (int s = 0; s < STRIP; s++) { accA[s] = 0.f; accC[s] = 0.f; }

    #pragma unroll 4
    for (int c = 0; c < CIN; c++) {
        float xv = xs[node][c];
        const float4* wt = reinterpret_cast<const float4*>(W + (size_t)c*COUT + co);
        const float4* wb = reinterpret_cast<const float4*>(W + (size_t)(CIN + c)*COUT + co);
        #pragma unroll
        for (int u = 0; u < STRIP/4; u++) {
            float4 t4 = __ldg(wt + u);
            float4 b4 = __ldg(wb + u);
            accA[4*u+0] = fmaf(xv, t4.x - b4.x, accA[4*u+0]);
            accA[4*u+1] = fmaf(xv, t4.y - b4.y, accA[4*u+1]);
            accA[4*u+2] = fmaf(xv, t4.z - b4.z, accA[4*u+2]);
            accA[4*u+3] = fmaf(xv, t4.w - b4.w, accA[4*u+3]);
            accC[4*u+0] = fmaf(xv, b4.x, accC[4*u+0]);
            accC[4*u+1] = fmaf(xv, b4.y, accC[4*u+1]);
            accC[4*u+2] = fmaf(xv, b4.z, accC[4*u+2]);
            accC[4*u+3] = fmaf(xv, b4.w, accC[4*u+3]);
        }
    }
    size_t rowo = (size_t)(nodeBase + node)*COUT + co;
    #pragma unroll
    for (int s = 0; s < STRIP; s++) {
        g_A[rowo + s] = accA[s] + bias[co + s];
        g_C[rowo + s] = accC[s];
    }
}

// ---------------- gather-max aggregate: out = A[i] + max_k C[knn(i,k)] ----------------
template<int COUT, int CATOFF>
__global__ void agg_kernel() {
    const int node = blockIdx.x;
    const int c = threadIdx.x;
    __shared__ int sidx[KK];
    if (c < KK) sidx[c] = g_knn[(size_t)node*KK + c];
    __syncthreads();
    const int jb = (node >> 12) << 12;   // batch base (NN = 4096)
    float m = -3.4e38f;
    #pragma unroll
    for (int k = 0; k < KK; k++)
        m = fmaxf(m, g_C[(size_t)(jb + sidx[k])*COUT + c]);
    g_xcat[(size_t)node*512 + CATOFF + c] = g_A[(size_t)node*COUT + c] + m;
}

// ---------------- final GEMM [BN,512]x[512,1024] fused with max over N ----------------
__global__ void __launch_bounds__(256) final_kernel(const float* __restrict__ Wf1,
                                                    const float* __restrict__ bf1) {
    __shared__ float As[16][132];   // [k][node]
    __shared__ float Bs[16][132];   // [k][out]
    __shared__ int cmax[128];

    const int tid = threadIdx.x;
    const int nodeBase = blockIdx.x * 128;
    const int outBase  = blockIdx.y * 128;
    const int rb = (tid >> 4) * 8;
    const int cb = (tid & 15) * 8;

    float acc[8][8];
    #pragma unroll
    for (int u = 0; u < 8; u++)
        #pragma unroll
        for (int v = 0; v < 8; v++) acc[u][v] = 0.f;

    for (int kc = 0; kc < 512; kc += 16) {
        __syncthreads();
        for (int e = tid; e < 128*16; e += 256) {
            int node = e >> 4, k = e & 15;
            As[k][node] = g_xcat[(size_t)(nodeBase + node)*512 + kc + k];
        }
        for (int e = tid; e < 16*128; e += 256) {
            int k = e >> 7, o = e & 127;
            Bs[k][o] = Wf1[(size_t)(kc + k)*1024 + outBase + o];
        }
        __syncthreads();
        #pragma unroll
        for (int k = 0; k < 16; k++) {
            float4 a0 = *reinterpret_cast<const float4*>(&As[k][rb]);
            float4 a1 = *reinterpret_cast<const float4*>(&As[k][rb+4]);
            float4 b0 = *reinterpret_cast<const float4*>(&Bs[k][cb]);
            float4 b1 = *reinterpret_cast<const float4*>(&Bs[k][cb+4]);
            float av[8] = {a0.x,a0.y,a0.z,a0.w,a1.x,a1.y,a1.z,a1.w};
            float bv[8] = {b0.x,b0.y,b0.z,b0.w,b1.x,b1.y,b1.z,b1.w};
            #pragma unroll
            for (int u = 0; u < 8; u++)
                #pragma unroll
                for (int v = 0; v < 8; v++) acc[u][v] = fmaf(av[u], bv[v], acc[u][v]);
        }
    }

    if (tid < 128) cmax[tid] = ENC_NEG_INF;
    __syncthreads();

    const int b = nodeBase >> 12;
    #pragma unroll
    for (int v = 0; v < 8; v++) {
        float colm = -3.4e38f;
        #pragma unroll
        for (int u = 0; u < 8; u++) colm = fmaxf(colm, acc[u][v]);
        colm += bf1[outBase + cb + v];
        atomicMax(&cmax[cb + v], encf(colm));
    }
    __syncthreads();
    if (tid < 128) atomicMax(&g_pool_enc[b*1024 + outBase + tid], cmax[tid]);
}

// ---------------- head ----------------
__global__ void head1_kernel(const float* __restrict__ Wa, const float* __restrict__ ba) {
    const int b = blockIdx.x, o = threadIdx.x;   // 512 threads
    __shared__ float p[1024];
    for (int e = o; e < 1024; e += 512) p[e] = decf(g_pool_enc[b*1024 + e]);
    __syncthreads();
    float acc = ba[o];
    #pragma unroll 8
    for (int in = 0; in < 1024; in++) acc = fmaf(p[in], Wa[(size_t)in*512 + o], acc);
    g_h1[b*512 + o] = fmaxf(acc, 0.f);
}

__global__ void head2_kernel(const float* __restrict__ Wb, const float* __restrict__ bb) {
    const int b = blockIdx.x, o = threadIdx.x;   // 256 threads
    __shared__ float p[512];
    for (int e = o; e < 512; e += 256) p[e] = g_h1[b*512 + e];
    __syncthreads();
    float acc = bb[o];
    #pragma unroll 8
    for (int in = 0; in < 512; in++) acc = fmaf(p[in], Wb[(size_t)in*256 + o], acc);
    g_h2[b*256 + o] = fmaxf(acc, 0.f);
}

__global__ void head3_kernel(const float* __restrict__ Wc, const float* __restrict__ bc,
                             float* __restrict__ out) {
    const int b = blockIdx.x, t = threadIdx.x;   // 32 threads
    __shared__ float h[256];
    for (int e = t; e < 256; e += 32) h[e] = g_h2[b*256 + e];
    __syncthreads();
    float logit = -3.4e38f;
    if (t < 23) {
        logit = bc[t];
        #pragma unroll 8
        for (int in = 0; in < 256; in++) logit = fmaf(h[in], Wc[in*23 + t], logit);
    }
    float mx = logit;
    #pragma unroll
    for (int off = 16; off > 0; off >>= 1) mx = fmaxf(mx, __shfl_xor_sync(0xffffffffu, mx, off));
    float ex = (t < 23) ? expf(logit - mx) : 0.f;
    float s = ex;
    #pragma unroll
    for (int off = 16; off > 0; off >>= 1) s += __shfl_xor_sync(0xffffffffu, s, off);
    if (t < 23) out[b*23 + t] = logit - mx - logf(s);
}

// ---------------- launch ----------------
extern "C" void kernel_launch(void* const* d_in, const int* in_sizes, int n_in,
                              void* d_out, int out_size) {
    const float* pos = (const float*)d_in[0];
    const float* x   = (const float*)d_in[1];
    const float* W1  = (const float*)d_in[2];  const float* b1 = (const float*)d_in[3];
    const float* W2  = (const float*)d_in[4];  const float* b2 = (const float*)d_in[5];
    const float* W3  = (const float*)d_in[6];  const float* b3 = (const float*)d_in[7];
    const float* W4  = (const float*)d_in[8];  const float* b4 = (const float*)d_in[9];
    const float* Wf1 = (const float*)d_in[10]; const float* bf1 = (const float*)d_in[11];
    const float* Wa  = (const float*)d_in[12]; const float* ba = (const float*)d_in[13];
    const float* Wb  = (const float*)d_in[14]; const float* bb = (const float*)d_in[15];
    const float* Wc  = (const float*)d_in[16]; const float* bc = (const float*)d_in[17];
    float* out = (float*)d_out;

    // allow >48KB dynamic smem where needed (host-side config, not a stream op;
    // legal during graph capture and idempotent across calls)
    cudaFuncSetAttribute(knn_kernel<6,   6,   true,  0>,   cudaFuncAttributeMaxDynamicSharedMemorySize, knn_smem_bytes<6>());
    cudaFuncSetAttribute(knn_kernel<64,  512, false, 0>,   cudaFuncAttributeMaxDynamicSharedMemorySize, knn_smem_bytes<64>());
    cudaFuncSetAttribute(knn_kernel<64,  512, false, 64>,  cudaFuncAttributeMaxDynamicSharedMemorySize, knn_smem_bytes<64>());
    cudaFuncSetAttribute(knn_kernel<128, 512, false, 128>, cudaFuncAttributeMaxDynamicSharedMemorySize, knn_smem_bytes<128>());

    build_x0_kernel<<<(BN*6 + 255)/256, 256>>>(pos, x);
    init_pool_kernel<<<(BB*1024 + 255)/256, 256>>>();

    // layer 1: x0 (CIN=6, stride 6) -> x1 (64) @ cat offset 0
    sq_kernel<6, 6, true, 0><<<BN/256, 256>>>();
    knn_kernel<6, 6, true, 0><<<dim3(NN/64, BB), 64, knn_smem_bytes<6>()>>>();
    proj_kernel<6, 6, true, 0, 64><<<BN/16, 256>>>(W1, b1);
    agg_kernel<64, 0><<<BN, 64>>>();

    // layer 2: x1 (CIN=64, stride 512, off 0) -> x2 (64) @ cat offset 64
    sq_kernel<64, 512, false, 0><<<BN/256, 256>>>();
    knn_kernel<64, 512, false, 0><<<dim3(NN/64, BB), 64, knn_smem_bytes<64>()>>>();
    proj_kernel<64, 512, false, 0, 64><<<BN/16, 256>>>(W2, b2);
    agg_kernel<64, 64><<<BN, 64>>>();

    // layer 3: x2 (CIN=64, off 64) -> x3 (128) @ cat offset 128
    sq_kernel<64, 512, false, 64><<<BN/256, 256>>>();
    knn_kernel<64, 512, false, 64><<<dim3(NN/64, BB), 64, knn_smem_bytes<64>()>>>();
    proj_kernel<64, 512, false, 64, 128><<<BN/16, 256>>>(W3, b3);
    agg_kernel<128, 128><<<BN, 128>>>();

    // layer 4: x3 (CIN=128, off 128) -> x4 (256) @ cat offset 256
    sq_kernel<128, 512, false, 128><<<BN/256, 256>>>();
    knn_kernel<128, 512, false, 128><<<dim3(NN/64, BB), 64, knn_smem_bytes<128>()>>>();
    proj_kernel<128, 512, false, 128, 256><<<BN/16, 256>>>(W4, b4);
    agg_kernel<256, 256><<<BN, 256>>>();

    // final feature GEMM + global max-pool
    final_kernel<<<dim3(BN/128, 1024/128), 256>>>(Wf1, bf1);

    // head
    head1_kernel<<<BB, 512>>>(Wa, ba);
    head2_kernel<<<BB, 256>>>(Wb, bb);
    head3_kernel<<<BB, 32>>>(Wc, bc, out);
}

// round 16
// speedup vs baseline: 1.5548x; 1.0099x over previous
#include <cuda_runtime.h>
#include <cuda_bf16.h>
#include <mma.h>
#include <cstdint>
#include <stdint.h>
#include <math.h>

using namespace nvcuda;

#define BB 8
#define NN 4096
#define KK 20
#define BN (BB*NN)

// ---------------- scratch (static device globals; no runtime alloc) ----------------
__device__ float g_x0[BN*6];
__device__ float g_xcat[(size_t)BN*512];
__device__ float g_A[(size_t)BN*256];
__device__ float g_C[(size_t)BN*256];
__device__ float g_sq[BN];
__device__ int   g_knn[BN*KK];
__device__ int   g_pool_enc[BB*1024];
__device__ float g_h1[BB*512];
__device__ float g_h2[BB*256];
// bf16 hi/lo splits for the tensor-core final GEMM
__device__ __nv_bfloat16 g_xh[(size_t)BN*512];
__device__ __nv_bfloat16 g_xl[(size_t)BN*512];
__device__ __nv_bfloat16 g_wth[1024*512];   // Wf1 transposed [n][k], hi
__device__ __nv_bfloat16 g_wtl[1024*512];   // lo

__device__ __forceinline__ int   encf(float f){ int i=__float_as_int(f); return i>=0 ? i : i^0x7FFFFFFF; }
__device__ __forceinline__ float decf(int i){ return __int_as_float(i>=0 ? i : i^0x7FFFFFFF); }
#define ENC_NEG_INF (-2139095041)  /* encf(-inf) = 0x807FFFFF */

// ---------------- build x0 = concat(pos, x) ----------------
__global__ void build_x0_kernel(const float* __restrict__ pos, const float* __restrict__ x) {
    int g = blockIdx.x * 256 + threadIdx.x;
    if (g >= BN*6) return;
    int n = g / 6, c = g - n*6;
    g_x0[g] = (c < 3) ? pos[n*3 + c] : x[n*3 + c - 3];
}

__global__ void init_pool_kernel() {
    int g = blockIdx.x * 256 + threadIdx.x;
    if (g < BB*1024) g_pool_enc[g] = ENC_NEG_INF;
}

// ---------------- squared norms ----------------
template<int CIN, int SIN, bool USE_X0, int INOFF>
__global__ void sq_kernel() {
    int g = blockIdx.x * 256 + threadIdx.x;
    if (g >= BN) return;
    const float* base = USE_X0 ? g_x0 : (g_xcat + INOFF);
    const float* xr = base + (size_t)g * SIN;
    float s = 0.f;
    #pragma unroll 8
    for (int c = 0; c < CIN; c++) { float v = xr[c]; s += v*v; }
    g_sq[g] = s;
}

// ---------------- kNN: 4-nodes-per-thread register-blocked gram + packed-key top-20 ----
template<int CIN> __host__ __device__ constexpr int knn_xis_stride() { return CIN + 4; }
template<int CIN> __host__ __device__ constexpr int knn_xj_stride()  { return 8*CIN + 4; }
template<int CIN> __host__ __device__ constexpr int knn_xj_region()  {
    return (4*knn_xj_stride<CIN>() > 192*KK) ? 4*knn_xj_stride<CIN>() : 192*KK;
}
template<int CIN> __host__ __device__ constexpr int knn_smem_bytes() {
    return (64*knn_xis_stride<CIN>() + knn_xj_region<CIN>()) * 4;
}

template<int CIN, int SIN, bool USE_X0, int INOFF>
__global__ void __launch_bounds__(64, 4) knn_kernel() {
    constexpr int TI = 64, SPLIT = 4, TJ = 8, RN = 4;
    constexpr int JSEG = NN / SPLIT;                 // 1024
    constexpr int XIS_STRIDE = knn_xis_stride<CIN>();
    constexpr int XJ_STRIDE  = knn_xj_stride<CIN>();

    extern __shared__ float smem[];
    float* Xis = smem;                               // TI * XIS_STRIDE
    float* Xjs = smem + TI*XIS_STRIDE;               // XJ region (reused for merge)
    __shared__ float sqj_s[SPLIT*TJ];

    const int b    = blockIdx.y;
    const int tid  = threadIdx.x;
    const int quad = tid >> 2;       // 0..15
    const int sp   = tid & 3;        // split 0..3
    const float* base = USE_X0 ? g_x0 : (g_xcat + INOFF);
    const float* Xb = base + (size_t)b * NN * SIN;

    if (CIN % 4 == 0) {
        for (int e = tid; e < TI*(CIN/4); e += 64) {
            int r = e / (CIN/4), c4 = e - r*(CIN/4);
            float4 v = *reinterpret_cast<const float4*>(&Xb[(size_t)(blockIdx.x*TI + r)*SIN + c4*4]);
            *reinterpret_cast<float4*>(&Xis[r*XIS_STRIDE + c4*4]) = v;
        }
    } else {
        for (int e = tid; e < TI*CIN; e += 64) {
            int r = e / CIN, c = e - r*CIN;
            Xis[r*XIS_STRIDE + c] = Xb[(size_t)(blockIdx.x*TI + r)*SIN + c];
        }
    }

    int kd[RN][KK];
    #pragma unroll
    for (int n = 0; n < RN; n++)
        #pragma unroll
        for (int k = 0; k < KK; k++) kd[n][k] = 0x7FFFFFFF;
    int thr[RN];
    #pragma unroll
    for (int n = 0; n < RN; n++) thr[n] = 0x7FFFFFFF;

    const int jbase = sp * JSEG;
    const float* xj = Xjs + sp*XJ_STRIDE;

    for (int jo = 0; jo < JSEG; jo += TJ) {
        __syncthreads();
        if (CIN % 4 == 0) {
            for (int e = tid; e < SPLIT*TJ*(CIN/4); e += 64) {
                int s = e / (TJ*(CIN/4));
                int rem = e - s*(TJ*(CIN/4));
                int r = rem / (CIN/4), c4 = rem - r*(CIN/4);
                float4 v = *reinterpret_cast<const float4*>(&Xb[(size_t)(s*JSEG + jo + r)*SIN + c4*4]);
                *reinterpret_cast<float4*>(&Xjs[s*XJ_STRIDE + r*CIN + c4*4]) = v;
            }
        } else {
            for (int e = tid; e < SPLIT*TJ*CIN; e += 64) {
                int s = e / (TJ*CIN);
                int rem = e - s*(TJ*CIN);
                int r = rem / CIN, c = rem - r*CIN;
                Xjs[s*XJ_STRIDE + r*CIN + c] = Xb[(size_t)(s*JSEG + jo + r)*SIN + c];
            }
        }
        if (tid < SPLIT*TJ)
            sqj_s[tid] = g_sq[b*NN + (tid>>3)*JSEG + jo + (tid&7)];
        __syncthreads();

        float acc[RN][TJ];
        #pragma unroll
        for (int n = 0; n < RN; n++)
            #pragma unroll
            for (int j = 0; j < TJ; j++) acc[n][j] = 0.f;

        if (CIN % 4 == 0) {
            #pragma unroll 4
            for (int c4 = 0; c4 < CIN/4; c4++) {
                float4 A[RN];
                #pragma unroll
                for (int n = 0; n < RN; n++)
                    A[n] = *reinterpret_cast<const float4*>(&Xis[(quad + 16*n)*XIS_STRIDE + c4*4]);
                #pragma unroll
                for (int j = 0; j < TJ; j++) {
                    const float4 b4 = *reinterpret_cast<const float4*>(&xj[j*CIN + c4*4]);
                    #pragma unroll
                    for (int n = 0; n < RN; n++) {
                        acc[n][j] = fmaf(A[n].x, b4.x, acc[n][j]);
                        acc[n][j] = fmaf(A[n].y, b4.y, acc[n][j]);
                        acc[n][j] = fmaf(A[n].z, b4.z, acc[n][j]);
                        acc[n][j] = fmaf(A[n].w, b4.w, acc[n][j]);
                    }
                }
            }
        } else {
            #pragma unroll
            for (int c = 0; c < CIN; c++) {
                float a[RN];
                #pragma unroll
                for (int n = 0; n < RN; n++) a[n] = Xis[(quad + 16*n)*XIS_STRIDE + c];
                #pragma unroll
                for (int j = 0; j < TJ; j++) {
                    const float bv = xj[j*CIN + c];
                    #pragma unroll
                    for (int n = 0; n < RN; n++) acc[n][j] = fmaf(a[n], bv, acc[n][j]);
                }
            }
        }

        #pragma unroll
        for (int j = 0; j < TJ; j++) {
            const float sj = sqj_s[sp*TJ + j];
            const int jidx = jbase + jo + j;
            #pragma unroll
            for (int n = 0; n < RN; n++) {
                float r2 = fmaf(-2.f, acc[n][j], sj);
                int e = __float_as_int(r2);
                e ^= (int)(((unsigned)(e >> 31)) >> 1);
                int key = (e & ~0xFFF) | jidx;
                if (key < thr[n]) {
                    int cd = key;
                    #pragma unroll
                    for (int k = 0; k < KK; k++) {
                        const int lo = min(kd[n][k], cd);
                        const int hi = max(kd[n][k], cd);
                        kd[n][k] = lo; cd = hi;
                    }
                }
            }
        }

        #pragma unroll
        for (int n = 0; n < RN; n++) {
            int w = kd[n][KK-1];
            w = min(w, __shfl_xor_sync(0xffffffffu, w, 1));
            w = min(w, __shfl_xor_sync(0xffffffffu, w, 2));
            thr[n] = w;
        }
    }

    __syncthreads();
    int* md = (int*)Xjs;
    if (sp != 0) {
        #pragma unroll
        for (int n = 0; n < RN; n++) {
            const int o = ((quad + 16*n)*3 + (sp-1))*KK;
            #pragma unroll
            for (int k = 0; k < KK; k++) md[o+k] = kd[n][k];
        }
    }
    __syncthreads();
    if (sp == 0) {
        #pragma unroll
        for (int n = 0; n < RN; n++) {
            const int nl = quad + 16*n;
            int worst = kd[n][KK-1];
            for (int s = 0; s < 3; s++) {
                const int o = (nl*3 + s)*KK;
                for (int k = 0; k < KK; k++) {
                    int cd = md[o+k];
                    if (cd >= worst) break;
                    #pragma unroll
                    for (int kk = 0; kk < KK; kk++) {
                        const int lo = min(kd[n][kk], cd);
                        const int hi = max(kd[n][kk], cd);
                        kd[n][kk] = lo; cd = hi;
                    }
                    worst = kd[n][KK-1];
                }
            }
            int* dst = g_knn + (size_t)(b*NN + blockIdx.x*TI + nl)*KK;
            #pragma unroll
            for (int k = 0; k < KK; k++) dst[k] = kd[n][k] & 0xFFF;
        }
    }
}

// ---------------- per-node projections: A = X(Wt-Wb)+b, C = X Wb ----------------
template<int CIN, int SIN, bool USE_X0, int INOFF, int COUT>
__global__ void __launch_bounds__(256) proj_kernel(const float* __restrict__ W,
                                                   const float* __restrict__ bias) {
    constexpr int TM = 16;
    constexpr int STRIP = COUT / 16;
    __shared__ float xs[TM][CIN];

    const int nodeBase = blockIdx.x * TM;
    const int tid = threadIdx.x;
    const float* base = USE_X0 ? g_x0 : (g_xcat + INOFF);

    for (int e = tid; e < TM*CIN; e += 256) {
        int r = e / CIN, c = e - r*CIN;
        xs[r][c] = base[(size_t)(nodeBase + r)*SIN + c];
    }
    __syncthreads();

    const int node = tid >> 4;
    const int cg   = tid & 15;
    const int co   = cg * STRIP;

    float accA[STRIP], accC[STRIP];
    #pragma unroll
    for (int s = 0; s < STRIP; s++) { accA[s] = 0.f; accC[s] = 0.f; }

    #pragma unroll 4
    for (int c = 0; c < CIN; c++) {
        float xv = xs[node][c];
        const float4* wt = reinterpret_cast<const float4*>(W + (size_t)c*COUT + co);
        const float4* wb = reinterpret_cast<const float4*>(W + (size_t)(CIN + c)*COUT + co);
        #pragma unroll
        for (int u = 0; u < STRIP/4; u++) {
            float4 t4 = __ldg(wt + u);
            float4 b4 = __ldg(wb + u);
            accA[4*u+0] = fmaf(xv, t4.x - b4.x, accA[4*u+0]);
            accA[4*u+1] = fmaf(xv, t4.y - b4.y, accA[4*u+1]);
            accA[4*u+2] = fmaf(xv, t4.z - b4.z, accA[4*u+2]);
            accA[4*u+3] = fmaf(xv, t4.w - b4.w, accA[4*u+3]);
            accC[4*u+0] = fmaf(xv, b4.x, accC[4*u+0]);
            accC[4*u+1] = fmaf(xv, b4.y, accC[4*u+1]);
            accC[4*u+2] = fmaf(xv, b4.z, accC[4*u+2]);
            accC[4*u+3] = fmaf(xv, b4.w, accC[4*u+3]);
        }
    }
    size_t rowo = (size_t)(nodeBase + node)*COUT + co;
    #pragma unroll
    for (int s = 0; s < STRIP; s++) {
        g_A[rowo + s] = accA[s] + bias[co + s];
        g_C[rowo + s] = accC[s];
    }
}

// ---------------- gather-max aggregate: out = A[i] + max_k C[knn(i,k)] ----------------
template<int COUT, int CATOFF>
__global__ void agg_kernel() {
    const int node = blockIdx.x;
    const int c = threadIdx.x;
    __shared__ int sidx[KK];
    if (c < KK) sidx[c] = g_knn[(size_t)node*KK + c];
    __syncthreads();
    const int jb = (node >> 12) << 12;
    float m = -3.4e38f;
    #pragma unroll
    for (int k = 0; k < KK; k++)
        m = fmaxf(m, g_C[(size_t)(jb + sidx[k])*COUT + c]);
    g_xcat[(size_t)node*512 + CATOFF + c] = g_A[(size_t)node*COUT + c] + m;
}

// ---------------- bf16 hi/lo splits for the tensor-core final GEMM ----------------
__global__ void split_x_kernel() {
    size_t idx = (size_t)blockIdx.x*256 + threadIdx.x;
    if (idx >= (size_t)BN*512) return;
    float v = g_xcat[idx];
    __nv_bfloat16 hi = __float2bfloat16(v);
    g_xh[idx] = hi;
    g_xl[idx] = __float2bfloat16(v - __bfloat162float(hi));
}

__global__ void split_w_kernel(const float* __restrict__ Wf1) {
    int idx = blockIdx.x*256 + threadIdx.x;      // over 1024*512
    if (idx >= 1024*512) return;
    int n = idx >> 9, k = idx & 511;             // transposed: row n, col k
    float v = Wf1[(size_t)k*1024 + n];
    __nv_bfloat16 hi = __float2bfloat16(v);
    g_wth[idx] = hi;
    g_wtl[idx] = __float2bfloat16(v - __bfloat162float(hi));
}

// ---------------- final GEMM via WMMA bf16x3 (HMMA) + fused max-pool ----------------
// Block: 256 threads (8 warps), output tile 128 rows x 128 cols.
// Warp w: rows (w&3)*32 (2 frags), cols (w>>2)*64 (4 frags) -> 2x4 acc frags.
// K loop over 512 in 16-steps; 3 precision passes (hi*hi + hi*lo + lo*hi),
// fp32 accumulators. A row-major from g_xh/g_xl; B col-major straight from
// the [n][k]-transposed g_wth/g_wtl (ld=512). Epilogue: store to padded smem,
// 128-thread column max, bias, encoded atomicMax into g_pool_enc.
#define FW_LD 144                        /* smem row stride (floats), mult of 16 */
#define FW_SMEM (128*FW_LD*4)

__global__ void __launch_bounds__(256) final_wmma_kernel(const float* __restrict__ bf1) {
    extern __shared__ float fsm[];
    const int tid = threadIdx.x;
    const int wid = tid >> 5;
    const int nodeBase = blockIdx.x * 128;
    const int outBase  = blockIdx.y * 128;
    const int wr = (wid & 3) * 32;       // warp row offset in tile
    const int wc = (wid >> 2) * 64;      // warp col offset in tile

    wmma::fragment<wmma::accumulator, 16, 16, 16, float> acc[2][4];
    #pragma unroll
    for (int i = 0; i < 2; i++)
        #pragma unroll
        for (int j = 0; j < 4; j++) wmma::fill_fragment(acc[i][j], 0.f);

    const __nv_bfloat16* arow_h = g_xh + (size_t)(nodeBase + wr)*512;
    const __nv_bfloat16* arow_l = g_xl + (size_t)(nodeBase + wr)*512;
    const __nv_bfloat16* bcol_h = g_wth + (size_t)(outBase + wc)*512;
    const __nv_bfloat16* bcol_l = g_wtl + (size_t)(outBase + wc)*512;

    for (int k = 0; k < 512; k += 16) {
        wmma::fragment<wmma::matrix_a, 16, 16, 16, __nv_bfloat16, wmma::row_major> ah[2], al[2];
        wmma::fragment<wmma::matrix_b, 16, 16, 16, __nv_bfloat16, wmma::col_major> bh[4], bl[4];
        #pragma unroll
        for (int i = 0; i < 2; i++) {
            wmma::load_matrix_sync(ah[i], arow_h + (size_t)i*16*512 + k, 512);
            wmma::load_matrix_sync(al[i], arow_l + (size_t)i*16*512 + k, 512);
        }
        #pragma unroll
        for (int j = 0; j < 4; j++) {
            wmma::load_matrix_sync(bh[j], bcol_h + (size_t)j*16*512 + k, 512);
            wmma::load_matrix_sync(bl[j], bcol_l + (size_t)j*16*512 + k, 512);
        }
        #pragma unroll
        for (int i = 0; i < 2; i++)
            #pragma unroll
            for (int j = 0; j < 4; j++) {
                wmma::mma_sync(acc[i][j], ah[i], bh[j], acc[i][j]);
                wmma::mma_sync(acc[i][j], ah[i], bl[j], acc[i][j]);
                wmma::mma_sync(acc[i][j], al[i], bh[j], acc[i][j]);
            }
    }

    #pragma unroll
    for (int i = 0; i < 2; i++)
        #pragma unroll
        for (int j = 0; j < 4; j++)
            wmma::store_matrix_sync(fsm + (size_t)(wr + i*16)*FW_LD + wc + j*16,
                                    acc[i][j], FW_LD, wmma::mem_row_major);
    __syncthreads();

    if (tid < 128) {
        float m = -3.4e38f;
        #pragma unroll 8
        for (int r = 0; r < 128; r++)
            m = fmaxf(m, fsm[(size_t)r*FW_LD + tid]);
        m += bf1[outBase + tid];
        atomicMax(&g_pool_enc[(nodeBase >> 12)*1024 + outBase + tid], encf(m));
    }
}

// ---------------- head ----------------
__global__ void head1_kernel(const float* __restrict__ Wa, const float* __restrict__ ba) {
    const int b = blockIdx.x, o = threadIdx.x;   // 512 threads
    __shared__ float p[1024];
    for (int e = o; e < 1024; e += 512) p[e] = decf(g_pool_enc[b*1024 + e]);
    __syncthreads();
    float acc = ba[o];
    #pragma unroll 8
    for (int in = 0; in < 1024; in++) acc = fmaf(p[in], Wa[(size_t)in*512 + o], acc);
    g_h1[b*512 + o] = fmaxf(acc, 0.f);
}

__global__ void head2_kernel(const float* __restrict__ Wb, const float* __restrict__ bb) {
    const int b = blockIdx.x, o = threadIdx.x;   // 256 threads
    __shared__ float p[512];
    for (int e = o; e < 512; e += 256) p[e] = g_h1[b*512 + e];
    __syncthreads();
    float acc = bb[o];
    #pragma unroll 8
    for (int in = 0; in < 512; in++) acc = fmaf(p[in], Wb[(size_t)in*256 + o], acc);
    g_h2[b*256 + o] = fmaxf(acc, 0.f);
}

__global__ void head3_kernel(const float* __restrict__ Wc, const float* __restrict__ bc,
                             float* __restrict__ out) {
    const int b = blockIdx.x, t = threadIdx.x;   // 32 threads
    __shared__ float h[256];
    for (int e = t; e < 256; e += 32) h[e] = g_h2[b*256 + e];
    __syncthreads();
    float logit = -3.4e38f;
    if (t < 23) {
        logit = bc[t];
        #pragma unroll 8
        for (int in = 0; in < 256; in++) logit = fmaf(h[in], Wc[in*23 + t], logit);
    }
    float mx = logit;
    #pragma unroll
    for (int off = 16; off > 0; off >>= 1) mx = fmaxf(mx, __shfl_xor_sync(0xffffffffu, mx, off));
    float ex = (t < 23) ? expf(logit - mx) : 0.f;
    float s = ex;
    #pragma unroll
    for (int off = 16; off > 0; off >>= 1) s += __shfl_xor_sync(0xffffffffu, s, off);
    if (t < 23) out[b*23 + t] = logit - mx - logf(s);
}

// ---------------- launch ----------------
extern "C" void kernel_launch(void* const* d_in, const int* in_sizes, int n_in,
                              void* d_out, int out_size) {
    const float* pos = (const float*)d_in[0];
    const float* x   = (const float*)d_in[1];
    const float* W1  = (const float*)d_in[2];  const float* b1 = (const float*)d_in[3];
    const float* W2  = (const float*)d_in[4];  const float* b2 = (const float*)d_in[5];
    const float* W3  = (const float*)d_in[6];  const float* b3 = (const float*)d_in[7];
    const float* W4  = (const float*)d_in[8];  const float* b4 = (const float*)d_in[9];
    const float* Wf1 = (const float*)d_in[10]; const float* bf1 = (const float*)d_in[11];
    const float* Wa  = (const float*)d_in[12]; const float* ba = (const float*)d_in[13];
    const float* Wb  = (const float*)d_in[14]; const float* bb = (const float*)d_in[15];
    const float* Wc  = (const float*)d_in[16]; const float* bc = (const float*)d_in[17];
    float* out = (float*)d_out;

    // host-side config (legal during capture, idempotent)
    cudaFuncSetAttribute(knn_kernel<6,   6,   true,  0>,   cudaFuncAttributeMaxDynamicSharedMemorySize, knn_smem_bytes<6>());
    cudaFuncSetAttribute(knn_kernel<64,  512, false, 0>,   cudaFuncAttributeMaxDynamicSharedMemorySize, knn_smem_bytes<64>());
    cudaFuncSetAttribute(knn_kernel<64,  512, false, 64>,  cudaFuncAttributeMaxDynamicSharedMemorySize, knn_smem_bytes<64>());
    cudaFuncSetAttribute(knn_kernel<128, 512, false, 128>, cudaFuncAttributeMaxDynamicSharedMemorySize, knn_smem_bytes<128>());
    cudaFuncSetAttribute(final_wmma_kernel, cudaFuncAttributeMaxDynamicSharedMemorySize, FW_SMEM);

    build_x0_kernel<<<(BN*6 + 255)/256, 256>>>(pos, x);
    init_pool_kernel<<<(BB*1024 + 255)/256, 256>>>();

    // layer 1: x0 (CIN=6) -> x1 (64) @ cat offset 0
    sq_kernel<6, 6, true, 0><<<BN/256, 256>>>();
    knn_kernel<6, 6, true, 0><<<dim3(NN/64, BB), 64, knn_smem_bytes<6>()>>>();
    proj_kernel<6, 6, true, 0, 64><<<BN/16, 256>>>(W1, b1);
    agg_kernel<64, 0><<<BN, 64>>>();

    // layer 2
    sq_kernel<64, 512, false, 0><<<BN/256, 256>>>();
    knn_kernel<64, 512, false, 0><<<dim3(NN/64, BB), 64, knn_smem_bytes<64>()>>>();
    proj_kernel<64, 512, false, 0, 64><<<BN/16, 256>>>(W2, b2);
    agg_kernel<64, 64><<<BN, 64>>>();

    // layer 3
    sq_kernel<64, 512, false, 64><<<BN/256, 256>>>();
    knn_kernel<64, 512, false, 64><<<dim3(NN/64, BB), 64, knn_smem_bytes<64>()>>>();
    proj_kernel<64, 512, false, 64, 128><<<BN/16, 256>>>(W3, b3);
    agg_kernel<128, 128><<<BN, 128>>>();

    // layer 4
    sq_kernel<128, 512, false, 128><<<BN/256, 256>>>();
    knn_kernel<128, 512, false, 128><<<dim3(NN/64, BB), 64, knn_smem_bytes<128>()>>>();
    proj_kernel<128, 512, false, 128, 256><<<BN/16, 256>>>(W4, b4);
    agg_kernel<256, 256><<<BN, 256>>>();

    // final feature GEMM (WMMA bf16x3) + global max-pool
    split_x_kernel<<<((size_t)BN*512 + 255)/256, 256>>>();
    split_w_kernel<<<(1024*512 + 255)/256, 256>>>(Wf1);
    final_wmma_kernel<<<dim3(BN/128, 1024/128), 256, FW_SMEM>>>(bf1);

    // head
    head1_kernel<<<BB, 512>>>(Wa, ba);
    head2_kernel<<<BB, 256>>>(Wb, bb);
    head3_kernel<<<BB, 32>>>(Wc, bc, out);
}